// round 2
// baseline (speedup 1.0000x reference)
#include <cuda_runtime.h>
#include <math.h>

#define B_   2
#define S_   2048
#define T_   4096      // B*S tokens
#define DIM_ 1024
#define H_   8

// ---------------- scratch (static device arrays; no allocs allowed) ----------
__device__ float g_cq[T_ * 128];        // normed q latent
__device__ float g_q[T_ * 1024];        // up-projected q (pre-rope)
__device__ float g_ckvkr[T_ * 192];     // dkv_kr output
__device__ float g_ckv[T_ * 128];       // normed kv latent
__device__ float g_krope[T_ * 64];      // roped k_rope
__device__ float g_kv[T_ * 2560];       // uk_uv output (k_nope | v)
__device__ float g_qs[16 * S_ * 128];   // q_states  [B*H, S, 128]
__device__ float g_ks[16 * S_ * 128];   // k_states  [B*H, S, 128]
__device__ float g_attn[T_ * 2048];     // attn out  [token, h*256+c]

// ---------------- generic tiled SGEMM: C = A[MxK] @ B[KxN] + bias -----------
// BM=BN=64, BK=16, 256 threads, 4x4 per-thread microtile.
__global__ void sgemm64(const float* __restrict__ A, const float* __restrict__ Bm,
                        const float* __restrict__ bias, float* __restrict__ C,
                        int M, int N, int K) {
    __shared__ float As[16][68];   // [k][m], padded
    __shared__ float Bs[16][68];   // [k][n], padded

    int tid = threadIdx.x;
    int tx = tid & 15, ty = tid >> 4;
    int row0 = blockIdx.y * 64;
    int col0 = blockIdx.x * 64;

    int ar = tid >> 2;          // A tile row 0..63
    int ac = (tid & 3) * 4;     // A tile col {0,4,8,12}
    int br = tid >> 4;          // B tile row 0..15
    int bc = (tid & 15) * 4;    // B tile col 0..60

    float acc[4][4];
    #pragma unroll
    for (int i = 0; i < 4; i++)
        #pragma unroll
        for (int j = 0; j < 4; j++) acc[i][j] = 0.f;

    for (int k0 = 0; k0 < K; k0 += 16) {
        float4 av = *(const float4*)(A + (size_t)(row0 + ar) * K + k0 + ac);
        float4 bv = *(const float4*)(Bm + (size_t)(k0 + br) * N + col0 + bc);
        As[ac + 0][ar] = av.x;
        As[ac + 1][ar] = av.y;
        As[ac + 2][ar] = av.z;
        As[ac + 3][ar] = av.w;
        *(float4*)&Bs[br][bc] = bv;
        __syncthreads();

        #pragma unroll
        for (int kk = 0; kk < 16; kk++) {
            float a[4], b[4];
            #pragma unroll
            for (int i = 0; i < 4; i++) { a[i] = As[kk][ty * 4 + i]; b[i] = Bs[kk][tx * 4 + i]; }
            #pragma unroll
            for (int i = 0; i < 4; i++)
                #pragma unroll
                for (int j = 0; j < 4; j++) acc[i][j] += a[i] * b[j];
        }
        __syncthreads();
    }

    #pragma unroll
    for (int i = 0; i < 4; i++) {
        #pragma unroll
        for (int j = 0; j < 4; j++) {
            int c = col0 + tx * 4 + j;
            C[(size_t)(row0 + ty * 4 + i) * N + c] = acc[i][j] + bias[c];
        }
    }
}

// ---------------- rmsnorm over a 128-wide row --------------------------------
__global__ void rmsnorm128(const float* __restrict__ src, int sstride,
                           float* __restrict__ dst, int dstride,
                           const float* __restrict__ w) {
    __shared__ float red[128];
    int t = blockIdx.x;
    int d = threadIdx.x;
    float v = src[(size_t)t * sstride + d];
    red[d] = v * v;
    __syncthreads();
    #pragma unroll
    for (int s = 64; s > 0; s >>= 1) {
        if (d < s) red[d] += red[d + s];
        __syncthreads();
    }
    float inv = rsqrtf(red[0] * (1.f / 128.f) + 1e-8f);
    dst[(size_t)t * dstride + d] = w[d] * v * inv;
}

// ---------------- rope for shared k_rope (hd=64) ------------------------------
__global__ void rope_k(const float* __restrict__ ckvkr, const int* __restrict__ pos_ids,
                       float* __restrict__ krope) {
    int t = blockIdx.x;
    int i = threadIdx.x;  // 0..31 pair index
    float pos = (float)pos_ids[t];
    float freq = powf(10000.f, -(float)(2 * i) / 64.f);
    float ang = pos * freq;
    float c = cosf(ang), s = sinf(ang);
    float xe = ckvkr[(size_t)t * 192 + 128 + 2 * i];
    float xo = ckvkr[(size_t)t * 192 + 128 + 2 * i + 1];
    krope[(size_t)t * 64 + 2 * i]     = xe * c - xo * s;
    krope[(size_t)t * 64 + 2 * i + 1] = xe * s + xo * c;
}

// ---------------- build q_states [B*H, S, 128] (nope | roped rope) -----------
__global__ void build_q(const float* __restrict__ q, const int* __restrict__ pos_ids,
                        float* __restrict__ qs) {
    int t = blockIdx.x;
    int d = threadIdx.x;  // 0..127
    int b = t >> 11, s = t & 2047;
    float pos = (float)pos_ids[t];
    #pragma unroll
    for (int h = 0; h < 8; h++) {
        float val;
        if (d < 96) {
            val = q[(size_t)t * 1024 + h * 96 + d];
        } else {
            int rr = d - 96;
            int i = rr >> 1;
            float freq = powf(10000.f, -(float)(2 * i) / 32.f);
            float ang = pos * freq;
            float c = cosf(ang), sn = sinf(ang);
            float xe = q[(size_t)t * 1024 + 768 + h * 32 + 2 * i];
            float xo = q[(size_t)t * 1024 + 768 + h * 32 + 2 * i + 1];
            val = (rr & 1) ? (xe * sn + xo * c) : (xe * c - xo * sn);
        }
        qs[(((size_t)(b * 8 + h)) * S_ + s) * 128 + d] = val;
    }
}

// ---------------- build k_states [B*H, S, 128] (k_nope | shared k_rope) ------
__global__ void build_k(const float* __restrict__ kv, const float* __restrict__ krope,
                        float* __restrict__ ks) {
    int t = blockIdx.x;
    int d = threadIdx.x;
    int b = t >> 11, s = t & 2047;
    #pragma unroll
    for (int h = 0; h < 8; h++) {
        float val = (d < 64) ? kv[(size_t)t * 2560 + h * 64 + d]
                             : krope[(size_t)t * 64 + (d - 64)];
        ks[(((size_t)(b * 8 + h)) * S_ + s) * 128 + d] = val;
    }
}

// ---------------- flash attention (fp32, no mask) -----------------------------
// grid (S/64, B*H), 256 threads. 64 queries x 64-key tiles, D=128, DV=256.
// smem: Qs 64x132, Ks 64x132, Vs 64x260, Ss 64x68 = 151552 bytes.
__global__ void flash_attn(const float* __restrict__ Qg, const float* __restrict__ Kg,
                           const float* __restrict__ KVg, float* __restrict__ Og) {
    extern __shared__ float sm[];
    float* Qs = sm;                 // 64*132
    float* Ks = Qs + 64 * 132;      // 64*132
    float* Vs = Ks + 64 * 132;      // 64*260
    float* Ss = Vs + 64 * 260;      // 64*68

    int tid = threadIdx.x;
    int bh = blockIdx.y;
    int b = bh >> 3, h = bh & 7;
    int q0 = blockIdx.x * 64;

    // load Q tile
    {
        const float* qbase = Qg + ((size_t)bh * S_ + q0) * 128;
        #pragma unroll
        for (int it = 0; it < 8; it++) {
            int e = it * 256 + tid;         // float4 index 0..2047
            int r = e >> 5;
            int c = (e & 31) * 4;
            *(float4*)&Qs[r * 132 + c] = *(const float4*)(qbase + (size_t)r * 128 + c);
        }
    }

    int ty = tid >> 4, tx = tid & 15;   // score-phase mapping
    int r = tid >> 2, q4 = tid & 3;     // softmax/PV mapping
    const float scale = 0.08838834764831845f;  // 1/sqrt(128)

    float m = -1e30f, l = 0.f;
    float acc[64];
    #pragma unroll
    for (int i = 0; i < 64; i++) acc[i] = 0.f;

    for (int kb = 0; kb < S_ / 64; kb++) {
        __syncthreads();  // prior-iteration consumers of Ks/Vs done; Qs visible on iter 0

        // load K tile
        const float* kbase = Kg + ((size_t)bh * S_ + kb * 64) * 128;
        #pragma unroll
        for (int it = 0; it < 8; it++) {
            int e = it * 256 + tid;
            int rr = e >> 5;
            int c = (e & 31) * 4;
            *(float4*)&Ks[rr * 132 + c] = *(const float4*)(kbase + (size_t)rr * 128 + c);
        }
        // load V tile (in-place from kv: v = kv[token, 512 + h*256 + c])
        const float* vbase = KVg + ((size_t)(b * S_ + kb * 64)) * 2560 + 512 + h * 256;
        #pragma unroll
        for (int it = 0; it < 16; it++) {
            int e = it * 256 + tid;
            int rr = e >> 6;
            int c = (e & 63) * 4;
            *(float4*)&Vs[rr * 260 + c] = *(const float4*)(vbase + (size_t)rr * 2560 + c);
        }
        __syncthreads();

        // scores: S = Q @ K^T * scale (each thread 4x4)
        float sc[4][4];
        #pragma unroll
        for (int i = 0; i < 4; i++)
            #pragma unroll
            for (int j = 0; j < 4; j++) sc[i][j] = 0.f;
        #pragma unroll 4
        for (int d = 0; d < 128; d++) {
            float a[4], bb[4];
            #pragma unroll
            for (int i = 0; i < 4; i++) {
                a[i] = Qs[(ty * 4 + i) * 132 + d];
                bb[i] = Ks[(tx * 4 + i) * 132 + d];
            }
            #pragma unroll
            for (int i = 0; i < 4; i++)
                #pragma unroll
                for (int j = 0; j < 4; j++) sc[i][j] += a[i] * bb[j];
        }
        #pragma unroll
        for (int i = 0; i < 4; i++)
            #pragma unroll
            for (int j = 0; j < 4; j++)
                Ss[(ty * 4 + i) * 68 + tx * 4 + j] = sc[i][j] * scale;
        // row r is written and read within the same warp (writers tid in
        // [(r/4)*16, +16), readers tid in [4r, 4r+4) -> same warp of 8 rows)
        __syncwarp();

        // online softmax update (4 threads per row)
        float tmax = -1e30f;
        #pragma unroll
        for (int c = 0; c < 16; c++) tmax = fmaxf(tmax, Ss[r * 68 + q4 * 16 + c]);
        tmax = fmaxf(tmax, __shfl_xor_sync(0xffffffffu, tmax, 1));
        tmax = fmaxf(tmax, __shfl_xor_sync(0xffffffffu, tmax, 2));
        float m_new = fmaxf(m, tmax);
        float alpha = expf(m - m_new);
        float tsum = 0.f;
        #pragma unroll
        for (int c = 0; c < 16; c++) {
            float p = expf(Ss[r * 68 + q4 * 16 + c] - m_new);
            Ss[r * 68 + q4 * 16 + c] = p;
            tsum += p;
        }
        tsum += __shfl_xor_sync(0xffffffffu, tsum, 1);
        tsum += __shfl_xor_sync(0xffffffffu, tsum, 2);
        l = l * alpha + tsum;
        m = m_new;
        #pragma unroll
        for (int i = 0; i < 64; i++) acc[i] *= alpha;
        __syncwarp();

        // PV: acc[row, owned cols] += P[row, k] * V[k, cols]
        // thread owns float4 chunks at word offsets i*16 + q4*4 (bank-spread)
        for (int k = 0; k < 64; k++) {
            float p = Ss[r * 68 + k];
            const float4* vr = (const float4*)(Vs + k * 260);
            #pragma unroll
            for (int i = 0; i < 16; i++) {
                float4 v = vr[i * 4 + q4];
                acc[i * 4 + 0] += p * v.x;
                acc[i * 4 + 1] += p * v.y;
                acc[i * 4 + 2] += p * v.z;
                acc[i * 4 + 3] += p * v.w;
            }
        }
    }

    // write attn scratch: [token, h*256 + c]
    float inv = 1.f / l;
    size_t orow = ((size_t)(b * S_ + q0 + r)) * 2048 + h * 256;
    #pragma unroll
    for (int i = 0; i < 16; i++) {
        float4 v = make_float4(acc[i * 4 + 0] * inv, acc[i * 4 + 1] * inv,
                               acc[i * 4 + 2] * inv, acc[i * 4 + 3] * inv);
        *(float4*)&Og[orow + i * 16 + q4 * 4] = v;
    }
}

// ---------------- launch -----------------------------------------------------
extern "C" void kernel_launch(void* const* d_in, const int* in_sizes, int n_in,
                              void* d_out, int out_size) {
    const float* x        = (const float*)d_in[0];
    const int*   pos      = (const int*)d_in[1];
    const float* w_dq_w   = (const float*)d_in[2];
    const float* w_dq_b   = (const float*)d_in[3];
    const float* q_norm_w = (const float*)d_in[4];
    const float* w_uq_w   = (const float*)d_in[5];
    const float* w_uq_b   = (const float*)d_in[6];
    const float* w_dkv_w  = (const float*)d_in[7];
    const float* w_dkv_b  = (const float*)d_in[8];
    const float* kv_norm_w= (const float*)d_in[9];
    const float* w_ukuv_w = (const float*)d_in[10];
    const float* w_ukuv_b = (const float*)d_in[11];
    const float* w_o_w    = (const float*)d_in[12];
    const float* w_o_b    = (const float*)d_in[13];
    float* out = (float*)d_out;

    float *cq, *q, *ckvkr, *ckv, *krope, *kv, *qs, *ks, *attn;
    cudaGetSymbolAddress((void**)&cq,    g_cq);
    cudaGetSymbolAddress((void**)&q,     g_q);
    cudaGetSymbolAddress((void**)&ckvkr, g_ckvkr);
    cudaGetSymbolAddress((void**)&ckv,   g_ckv);
    cudaGetSymbolAddress((void**)&krope, g_krope);
    cudaGetSymbolAddress((void**)&kv,    g_kv);
    cudaGetSymbolAddress((void**)&qs,    g_qs);
    cudaGetSymbolAddress((void**)&ks,    g_ks);
    cudaGetSymbolAddress((void**)&attn,  g_attn);

    // q path: cq = rmsnorm(x @ w_dq + b)
    sgemm64<<<dim3(128 / 64, T_ / 64), 256>>>(x, w_dq_w, w_dq_b, cq, T_, 128, DIM_);
    rmsnorm128<<<T_, 128>>>(cq, 128, cq, 128, q_norm_w);
    // q = cq @ w_uq + b
    sgemm64<<<dim3(1024 / 64, T_ / 64), 256>>>(cq, w_uq_w, w_uq_b, q, T_, 1024, 128);

    // kv path: ckv_kr = x @ w_dkv + b ; ckv = rmsnorm(first 128) ; krope = rope(last 64)
    sgemm64<<<dim3(192 / 64, T_ / 64), 256>>>(x, w_dkv_w, w_dkv_b, ckvkr, T_, 192, DIM_);
    rmsnorm128<<<T_, 128>>>(ckvkr, 192, ckv, 128, kv_norm_w);
    rope_k<<<T_, 32>>>(ckvkr, pos, krope);
    // kv = ckv @ w_ukuv + b
    sgemm64<<<dim3(2560 / 64, T_ / 64), 256>>>(ckv, w_ukuv_w, w_ukuv_b, kv, T_, 2560, 128);

    // gather into attention layouts
    build_q<<<T_, 128>>>(q, pos, qs);
    build_k<<<T_, 128>>>(kv, krope, ks);

    // flash attention
    cudaFuncSetAttribute(flash_attn, cudaFuncAttributeMaxDynamicSharedMemorySize, 151552);
    flash_attn<<<dim3(S_ / 64, 16), 256, 151552>>>(qs, ks, kv, attn);

    // output projection
    sgemm64<<<dim3(1024 / 64, T_ / 64), 256>>>(attn, w_o_w, w_o_b, out, T_, 1024, 2048);
}

// round 3
// speedup vs baseline: 7.2266x; 7.2266x over previous
#include <cuda_runtime.h>
#include <cuda_fp16.h>
#include <math.h>
#include <stdint.h>

#define B_   2
#define S_   2048
#define T_   4096      // B*S tokens
#define DIM_ 1024
#define H_   8

// ---------------- scratch (static device arrays; no allocs allowed) ----------
__device__ float  g_cq[T_ * 128];         // normed q latent (fp32)
__device__ float  g_q[T_ * 1024];         // up-projected q (pre-rope, fp32)
__device__ float  g_ckvkr[T_ * 192];      // dkv_kr output (fp32)
__device__ __half g_ckv_h[T_ * 128];      // normed kv latent (fp16)
__device__ float  g_krope[T_ * 64];       // roped k_rope (fp32)
__device__ __half g_kv_h[T_ * 2560];      // uk_uv output (k_nope | v) fp16
__device__ __half g_qs_h[16 * S_ * 128];  // q_states  [B*H, S, 128] fp16
__device__ __half g_ks_h[16 * S_ * 128];  // k_states  [B*H, S, 128] fp16
__device__ __half g_attn_h[T_ * 2048];    // attn out  [token, h*256+c] fp16
__device__ __half g_wukuv_h[128 * 2560];  // converted weights
__device__ __half g_wo_h[2048 * 1024];

// ---------------- mma/ldmatrix helpers ---------------------------------------
__device__ __forceinline__ uint32_t smem_u32(const void* p) {
    return (uint32_t)__cvta_generic_to_shared(p);
}
__device__ __forceinline__ void ldsm_x4(uint32_t* r, uint32_t addr) {
    asm volatile("ldmatrix.sync.aligned.m8n8.x4.shared.b16 {%0,%1,%2,%3},[%4];"
                 : "=r"(r[0]), "=r"(r[1]), "=r"(r[2]), "=r"(r[3]) : "r"(addr));
}
__device__ __forceinline__ void ldsm_x4_t(uint32_t* r, uint32_t addr) {
    asm volatile("ldmatrix.sync.aligned.m8n8.x4.trans.shared.b16 {%0,%1,%2,%3},[%4];"
                 : "=r"(r[0]), "=r"(r[1]), "=r"(r[2]), "=r"(r[3]) : "r"(addr));
}
__device__ __forceinline__ void mma16816(float* c, const uint32_t* a, const uint32_t* b) {
    asm volatile(
        "mma.sync.aligned.m16n8k16.row.col.f32.f16.f16.f32 "
        "{%0,%1,%2,%3},{%4,%5,%6,%7},{%8,%9},{%0,%1,%2,%3};"
        : "+f"(c[0]), "+f"(c[1]), "+f"(c[2]), "+f"(c[3])
        : "r"(a[0]), "r"(a[1]), "r"(a[2]), "r"(a[3]), "r"(b[0]), "r"(b[1]));
}
__device__ __forceinline__ uint32_t pack_h2(float lo, float hi) {
    __half2 h = __floats2half2_rn(lo, hi);
    return *(uint32_t*)&h;
}

// ---------------- f32 -> f16 convert ------------------------------------------
__global__ void f2h(const float* __restrict__ src, __half* __restrict__ dst, int n) {
    int i = blockIdx.x * blockDim.x + threadIdx.x;
    if (i < n) dst[i] = __float2half(src[i]);
}

// ---------------- generic tiled SGEMM (fp32, for small projections) ----------
__global__ void sgemm64(const float* __restrict__ A, const float* __restrict__ Bm,
                        const float* __restrict__ bias, float* __restrict__ C,
                        int M, int N, int K) {
    __shared__ float As[16][68];
    __shared__ float Bs[16][68];

    int tid = threadIdx.x;
    int tx = tid & 15, ty = tid >> 4;
    int row0 = blockIdx.y * 64;
    int col0 = blockIdx.x * 64;

    int ar = tid >> 2;
    int ac = (tid & 3) * 4;
    int br = tid >> 4;
    int bc = (tid & 15) * 4;

    float acc[4][4];
    #pragma unroll
    for (int i = 0; i < 4; i++)
        #pragma unroll
        for (int j = 0; j < 4; j++) acc[i][j] = 0.f;

    for (int k0 = 0; k0 < K; k0 += 16) {
        float4 av = *(const float4*)(A + (size_t)(row0 + ar) * K + k0 + ac);
        float4 bv = *(const float4*)(Bm + (size_t)(k0 + br) * N + col0 + bc);
        As[ac + 0][ar] = av.x;
        As[ac + 1][ar] = av.y;
        As[ac + 2][ar] = av.z;
        As[ac + 3][ar] = av.w;
        *(float4*)&Bs[br][bc] = bv;
        __syncthreads();

        #pragma unroll
        for (int kk = 0; kk < 16; kk++) {
            float a[4], b[4];
            #pragma unroll
            for (int i = 0; i < 4; i++) { a[i] = As[kk][ty * 4 + i]; b[i] = Bs[kk][tx * 4 + i]; }
            #pragma unroll
            for (int i = 0; i < 4; i++)
                #pragma unroll
                for (int j = 0; j < 4; j++) acc[i][j] += a[i] * b[j];
        }
        __syncthreads();
    }

    #pragma unroll
    for (int i = 0; i < 4; i++) {
        #pragma unroll
        for (int j = 0; j < 4; j++) {
            int c = col0 + tx * 4 + j;
            C[(size_t)(row0 + ty * 4 + i) * N + c] = acc[i][j] + bias[c];
        }
    }
}

// ---------------- fp16 tensor-core GEMM: C = A[MxK](h) @ B[KxN](h) + bias ----
// BM=128 BN=128 BK=32, 256 threads (8 warps, 2x4), warp tile 64x32.
template <typename OutT>
__global__ __launch_bounds__(256, 2) void hgemm(
    const __half* __restrict__ A, const __half* __restrict__ Bm,
    const float* __restrict__ bias, OutT* __restrict__ C, int M, int N, int K) {
    __shared__ __half As[128][40];   // pad 32->40: stride 80B, conflict-free ldmatrix
    __shared__ __half Bs[32][136];   // pad 128->136: stride 272B

    int tid = threadIdx.x, lane = tid & 31, w = tid >> 5;
    int wr = w >> 2, wc = w & 3;
    int row0 = blockIdx.y * 128, col0 = blockIdx.x * 128;

    float acc[16][4];
    #pragma unroll
    for (int i = 0; i < 16; i++)
        #pragma unroll
        for (int j = 0; j < 4; j++) acc[i][j] = 0.f;

    for (int k0 = 0; k0 < K; k0 += 32) {
        __syncthreads();
        // load A 128x32 (2 uint4 per thread)
        #pragma unroll
        for (int it = 0; it < 2; it++) {
            int e = it * 256 + tid;
            int r = e >> 2, c = (e & 3) * 8;
            *(uint4*)&As[r][c] = *(const uint4*)(A + (size_t)(row0 + r) * K + k0 + c);
        }
        // load B 32x128
        #pragma unroll
        for (int it = 0; it < 2; it++) {
            int e = it * 256 + tid;
            int r = e >> 4, c = (e & 15) * 8;
            *(uint4*)&Bs[r][c] = *(const uint4*)(Bm + (size_t)(k0 + r) * N + col0 + c);
        }
        __syncthreads();

        #pragma unroll
        for (int kk = 0; kk < 2; kk++) {
            uint32_t af[4][4], bf[2][4];
            #pragma unroll
            for (int mt = 0; mt < 4; mt++) {
                int r = wr * 64 + mt * 16 + (lane & 15);
                int c = kk * 16 + ((lane >> 4) << 3);
                ldsm_x4(af[mt], smem_u32(&As[r][c]));
            }
            #pragma unroll
            for (int nt2 = 0; nt2 < 2; nt2++) {
                int kr = kk * 16 + (lane & 7) + (lane & 8);
                int nc = wc * 32 + nt2 * 16 + ((lane >> 4) << 3);
                ldsm_x4_t(bf[nt2], smem_u32(&Bs[kr][nc]));
            }
            #pragma unroll
            for (int mt = 0; mt < 4; mt++)
                #pragma unroll
                for (int nt = 0; nt < 4; nt++)
                    mma16816(acc[mt * 4 + nt], af[mt], bf[nt >> 1] + (nt & 1) * 2);
        }
    }

    // epilogue
    #pragma unroll
    for (int mt = 0; mt < 4; mt++) {
        #pragma unroll
        for (int nt = 0; nt < 4; nt++) {
            int row = row0 + wr * 64 + mt * 16 + (lane >> 2);
            int col = col0 + wc * 32 + nt * 8 + (lane & 3) * 2;
            float b0 = bias[col], b1 = bias[col + 1];
            float v0 = acc[mt * 4 + nt][0] + b0;
            float v1 = acc[mt * 4 + nt][1] + b1;
            float v2 = acc[mt * 4 + nt][2] + b0;
            float v3 = acc[mt * 4 + nt][3] + b1;
            if (sizeof(OutT) == 2) {
                *(__half2*)((__half*)C + (size_t)row * N + col) = __floats2half2_rn(v0, v1);
                *(__half2*)((__half*)C + (size_t)(row + 8) * N + col) = __floats2half2_rn(v2, v3);
            } else {
                *(float2*)((float*)C + (size_t)row * N + col) = make_float2(v0, v1);
                *(float2*)((float*)C + (size_t)(row + 8) * N + col) = make_float2(v2, v3);
            }
        }
    }
}

// ---------------- rmsnorm over a 128-wide row --------------------------------
__global__ void rmsnorm128(const float* __restrict__ src, int sstride,
                           float* __restrict__ dst, int dstride,
                           const float* __restrict__ w) {
    __shared__ float red[128];
    int t = blockIdx.x;
    int d = threadIdx.x;
    float v = src[(size_t)t * sstride + d];
    red[d] = v * v;
    __syncthreads();
    #pragma unroll
    for (int s = 64; s > 0; s >>= 1) {
        if (d < s) red[d] += red[d + s];
        __syncthreads();
    }
    float inv = rsqrtf(red[0] * (1.f / 128.f) + 1e-8f);
    dst[(size_t)t * dstride + d] = w[d] * v * inv;
}

__global__ void rmsnorm128_h(const float* __restrict__ src, int sstride,
                             __half* __restrict__ dst, int dstride,
                             const float* __restrict__ w) {
    __shared__ float red[128];
    int t = blockIdx.x;
    int d = threadIdx.x;
    float v = src[(size_t)t * sstride + d];
    red[d] = v * v;
    __syncthreads();
    #pragma unroll
    for (int s = 64; s > 0; s >>= 1) {
        if (d < s) red[d] += red[d + s];
        __syncthreads();
    }
    float inv = rsqrtf(red[0] * (1.f / 128.f) + 1e-8f);
    dst[(size_t)t * dstride + d] = __float2half(w[d] * v * inv);
}

// ---------------- rope for shared k_rope (hd=64) ------------------------------
__global__ void rope_k(const float* __restrict__ ckvkr, const int* __restrict__ pos_ids,
                       float* __restrict__ krope) {
    int t = blockIdx.x;
    int i = threadIdx.x;  // 0..31 pair index
    float pos = (float)pos_ids[t];
    float freq = powf(10000.f, -(float)(2 * i) / 64.f);
    float ang = pos * freq;
    float c = cosf(ang), s = sinf(ang);
    float xe = ckvkr[(size_t)t * 192 + 128 + 2 * i];
    float xo = ckvkr[(size_t)t * 192 + 128 + 2 * i + 1];
    krope[(size_t)t * 64 + 2 * i]     = xe * c - xo * s;
    krope[(size_t)t * 64 + 2 * i + 1] = xe * s + xo * c;
}

// ---------------- build q_states [B*H, S, 128] fp16 --------------------------
__global__ void build_q(const float* __restrict__ q, const int* __restrict__ pos_ids,
                        __half* __restrict__ qs) {
    int t = blockIdx.x;
    int d = threadIdx.x;  // 0..127
    int b = t >> 11, s = t & 2047;
    float pos = (float)pos_ids[t];
    #pragma unroll
    for (int h = 0; h < 8; h++) {
        float val;
        if (d < 96) {
            val = q[(size_t)t * 1024 + h * 96 + d];
        } else {
            int rr = d - 96;
            int i = rr >> 1;
            float freq = powf(10000.f, -(float)(2 * i) / 32.f);
            float ang = pos * freq;
            float c = cosf(ang), sn = sinf(ang);
            float xe = q[(size_t)t * 1024 + 768 + h * 32 + 2 * i];
            float xo = q[(size_t)t * 1024 + 768 + h * 32 + 2 * i + 1];
            val = (rr & 1) ? (xe * sn + xo * c) : (xe * c - xo * sn);
        }
        qs[(((size_t)(b * 8 + h)) * S_ + s) * 128 + d] = __float2half(val);
    }
}

// ---------------- build k_states [B*H, S, 128] fp16 --------------------------
__global__ void build_k(const __half* __restrict__ kv, const float* __restrict__ krope,
                        __half* __restrict__ ks) {
    int t = blockIdx.x;
    int d = threadIdx.x;
    int b = t >> 11, s = t & 2047;
    __half kr;
    if (d >= 64) kr = __float2half(krope[(size_t)t * 64 + (d - 64)]);
    #pragma unroll
    for (int h = 0; h < 8; h++) {
        __half val = (d < 64) ? kv[(size_t)t * 2560 + h * 64 + d] : kr;
        ks[(((size_t)(b * 8 + h)) * S_ + s) * 128 + d] = val;
    }
}

// ---------------- fp16 tensor-core flash attention ---------------------------
// grid (S/64, B*H), 256 threads (8 warps). Warp w: row group w&3 (16 q rows),
// V half w>>2 (128 of 256 cols). Each warp computes full 16x64 scores (all keys).
#define QPITCH 136
#define VPITCH 264
__global__ __launch_bounds__(256, 1) void flash_fp16(
    const __half* __restrict__ Qg, const __half* __restrict__ Kg,
    const __half* __restrict__ KVg, __half* __restrict__ Og) {
    extern __shared__ __half sm[];
    __half* Qs = sm;                      // 64 x 136
    __half* Ks = Qs + 64 * QPITCH;        // 64 x 136
    __half* Vs = Ks + 64 * QPITCH;        // 64 x 264

    int tid = threadIdx.x, lane = tid & 31, w = tid >> 5;
    int qr = w & 3, vh = w >> 2;
    int bh = blockIdx.y;
    int b = bh >> 3, h = bh & 7;
    int q0 = blockIdx.x * 64;
    const float scale = 0.08838834764831845f;  // 1/sqrt(128)

    // load Q tile 64x128
    {
        const __half* qbase = Qg + ((size_t)bh * S_ + q0) * 128;
        #pragma unroll
        for (int it = 0; it < 4; it++) {
            int e = it * 256 + tid;
            int r = e >> 4, c = (e & 15) * 8;
            *(uint4*)&Qs[r * QPITCH + c] = *(const uint4*)(qbase + (size_t)r * 128 + c);
        }
    }
    __syncthreads();

    // Q fragments persistent in registers: 8 k-steps x 4 regs
    uint32_t qf[8][4];
    #pragma unroll
    for (int ks = 0; ks < 8; ks++) {
        int r = qr * 16 + (lane & 15);
        int c = ks * 16 + ((lane >> 4) << 3);
        ldsm_x4(qf[ks], smem_u32(&Qs[r * QPITCH + c]));
    }

    float m[2] = {-1e30f, -1e30f}, l[2] = {0.f, 0.f};
    float o[16][4];
    #pragma unroll
    for (int i = 0; i < 16; i++)
        #pragma unroll
        for (int j = 0; j < 4; j++) o[i][j] = 0.f;

    for (int kb = 0; kb < S_ / 64; kb++) {
        __syncthreads();
        // load K tile 64x128
        {
            const __half* kbase = Kg + ((size_t)bh * S_ + kb * 64) * 128;
            #pragma unroll
            for (int it = 0; it < 4; it++) {
                int e = it * 256 + tid;
                int r = e >> 4, c = (e & 15) * 8;
                *(uint4*)&Ks[r * QPITCH + c] = *(const uint4*)(kbase + (size_t)r * 128 + c);
            }
        }
        // load V tile 64x256 from kv_h: v = kv[token][512 + h*256 + c]
        {
            const __half* vbase = KVg + ((size_t)(b * S_ + kb * 64)) * 2560 + 512 + h * 256;
            #pragma unroll
            for (int it = 0; it < 8; it++) {
                int e = it * 256 + tid;
                int r = e >> 5, c = (e & 31) * 8;
                *(uint4*)&Vs[r * VPITCH + c] = *(const uint4*)(vbase + (size_t)r * 2560 + c);
            }
        }
        __syncthreads();

        // S = Q @ K^T  (16x64 per warp, 8 n-tiles)
        float s[8][4];
        #pragma unroll
        for (int i = 0; i < 8; i++)
            #pragma unroll
            for (int j = 0; j < 4; j++) s[i][j] = 0.f;
        #pragma unroll
        for (int ks = 0; ks < 8; ks++) {
            #pragma unroll
            for (int nt2 = 0; nt2 < 4; nt2++) {
                uint32_t bfr[4];
                int n = nt2 * 16 + ((lane >> 4) << 3) + (lane & 7);
                int k = ks * 16 + (lane & 8);
                ldsm_x4(bfr, smem_u32(&Ks[n * QPITCH + k]));
                mma16816(s[2 * nt2],     qf[ks], bfr + 0);
                mma16816(s[2 * nt2 + 1], qf[ks], bfr + 2);
            }
        }
        #pragma unroll
        for (int i = 0; i < 8; i++)
            #pragma unroll
            for (int j = 0; j < 4; j++) s[i][j] *= scale;

        // online softmax (rows: lane>>2 and lane>>2 + 8)
        #pragma unroll
        for (int rr = 0; rr < 2; rr++) {
            float mx = -1e30f;
            #pragma unroll
            for (int j = 0; j < 8; j++)
                mx = fmaxf(mx, fmaxf(s[j][2 * rr], s[j][2 * rr + 1]));
            mx = fmaxf(mx, __shfl_xor_sync(0xffffffffu, mx, 1));
            mx = fmaxf(mx, __shfl_xor_sync(0xffffffffu, mx, 2));
            float m_new = fmaxf(m[rr], mx);
            float alpha = __expf(m[rr] - m_new);
            float tsum = 0.f;
            #pragma unroll
            for (int j = 0; j < 8; j++) {
                float p0 = __expf(s[j][2 * rr] - m_new);
                float p1 = __expf(s[j][2 * rr + 1] - m_new);
                s[j][2 * rr] = p0;
                s[j][2 * rr + 1] = p1;
                tsum += p0 + p1;
            }
            tsum += __shfl_xor_sync(0xffffffffu, tsum, 1);
            tsum += __shfl_xor_sync(0xffffffffu, tsum, 2);
            l[rr] = l[rr] * alpha + tsum;
            m[rr] = m_new;
            #pragma unroll
            for (int j = 0; j < 16; j++) {
                o[j][2 * rr] *= alpha;
                o[j][2 * rr + 1] *= alpha;
            }
        }

        // P fragments (fp16) straight from registers
        uint32_t pf[4][4];
        #pragma unroll
        for (int kk = 0; kk < 4; kk++) {
            pf[kk][0] = pack_h2(s[2 * kk][0],     s[2 * kk][1]);
            pf[kk][1] = pack_h2(s[2 * kk][2],     s[2 * kk][3]);
            pf[kk][2] = pack_h2(s[2 * kk + 1][0], s[2 * kk + 1][1]);
            pf[kk][3] = pack_h2(s[2 * kk + 1][2], s[2 * kk + 1][3]);
        }

        // O += P @ V  (warp covers 128 V cols at offset vh*128)
        #pragma unroll
        for (int kk = 0; kk < 4; kk++) {
            #pragma unroll
            for (int nt2 = 0; nt2 < 8; nt2++) {
                uint32_t bfr[4];
                int k = kk * 16 + (lane & 7) + (lane & 8);
                int n = vh * 128 + nt2 * 16 + ((lane >> 4) << 3);
                ldsm_x4_t(bfr, smem_u32(&Vs[k * VPITCH + n]));
                mma16816(o[2 * nt2],     pf[kk], bfr + 0);
                mma16816(o[2 * nt2 + 1], pf[kk], bfr + 2);
            }
        }
    }

    // epilogue: write fp16 attn [token][h*256 + vh*128 + c]
    #pragma unroll
    for (int rr = 0; rr < 2; rr++) {
        float inv = 1.f / l[rr];
        int row = q0 + qr * 16 + (lane >> 2) + rr * 8;
        size_t base = ((size_t)(b * S_) + row) * 2048 + h * 256 + vh * 128;
        #pragma unroll
        for (int j = 0; j < 16; j++) {
            int c = j * 8 + (lane & 3) * 2;
            *(__half2*)&Og[base + c] =
                __floats2half2_rn(o[j][2 * rr] * inv, o[j][2 * rr + 1] * inv);
        }
    }
}

// ---------------- launch -----------------------------------------------------
extern "C" void kernel_launch(void* const* d_in, const int* in_sizes, int n_in,
                              void* d_out, int out_size) {
    const float* x        = (const float*)d_in[0];
    const int*   pos      = (const int*)d_in[1];
    const float* w_dq_w   = (const float*)d_in[2];
    const float* w_dq_b   = (const float*)d_in[3];
    const float* q_norm_w = (const float*)d_in[4];
    const float* w_uq_w   = (const float*)d_in[5];
    const float* w_uq_b   = (const float*)d_in[6];
    const float* w_dkv_w  = (const float*)d_in[7];
    const float* w_dkv_b  = (const float*)d_in[8];
    const float* kv_norm_w= (const float*)d_in[9];
    const float* w_ukuv_w = (const float*)d_in[10];
    const float* w_ukuv_b = (const float*)d_in[11];
    const float* w_o_w    = (const float*)d_in[12];
    const float* w_o_b    = (const float*)d_in[13];
    float* out = (float*)d_out;

    float *cq, *q, *ckvkr, *krope;
    __half *ckv_h, *kv_h, *qs_h, *ks_h, *attn_h, *wukuv_h, *wo_h;
    cudaGetSymbolAddress((void**)&cq,      g_cq);
    cudaGetSymbolAddress((void**)&q,       g_q);
    cudaGetSymbolAddress((void**)&ckvkr,   g_ckvkr);
    cudaGetSymbolAddress((void**)&krope,   g_krope);
    cudaGetSymbolAddress((void**)&ckv_h,   g_ckv_h);
    cudaGetSymbolAddress((void**)&kv_h,    g_kv_h);
    cudaGetSymbolAddress((void**)&qs_h,    g_qs_h);
    cudaGetSymbolAddress((void**)&ks_h,    g_ks_h);
    cudaGetSymbolAddress((void**)&attn_h,  g_attn_h);
    cudaGetSymbolAddress((void**)&wukuv_h, g_wukuv_h);
    cudaGetSymbolAddress((void**)&wo_h,    g_wo_h);

    // weight conversions (independent, launch first)
    f2h<<<(128 * 2560 + 255) / 256, 256>>>(w_ukuv_w, wukuv_h, 128 * 2560);
    f2h<<<(2048 * 1024 + 255) / 256, 256>>>(w_o_w, wo_h, 2048 * 1024);

    // q path: cq = rmsnorm(x @ w_dq + b); q = cq @ w_uq + b  (fp32)
    sgemm64<<<dim3(128 / 64, T_ / 64), 256>>>(x, w_dq_w, w_dq_b, cq, T_, 128, DIM_);
    rmsnorm128<<<T_, 128>>>(cq, 128, cq, 128, q_norm_w);
    sgemm64<<<dim3(1024 / 64, T_ / 64), 256>>>(cq, w_uq_w, w_uq_b, q, T_, 1024, 128);

    // kv path
    sgemm64<<<dim3(192 / 64, T_ / 64), 256>>>(x, w_dkv_w, w_dkv_b, ckvkr, T_, 192, DIM_);
    rmsnorm128_h<<<T_, 128>>>(ckvkr, 192, ckv_h, 128, kv_norm_w);
    rope_k<<<T_, 32>>>(ckvkr, pos, krope);
    // kv = ckv @ w_ukuv + b  (fp16 tensor cores, fp16 out)
    hgemm<__half><<<dim3(2560 / 128, T_ / 128), 256>>>(ckv_h, wukuv_h, w_ukuv_b, kv_h,
                                                       T_, 2560, 128);

    // gather into attention layouts (fp16)
    build_q<<<T_, 128>>>(q, pos, qs_h);
    build_k<<<T_, 128>>>(kv_h, krope, ks_h);

    // flash attention (fp16 tensor cores)
    cudaFuncSetAttribute(flash_fp16, cudaFuncAttributeMaxDynamicSharedMemorySize,
                         (64 * QPITCH * 2 + 64 * VPITCH) * (int)sizeof(__half));
    flash_fp16<<<dim3(S_ / 64, 16), 256,
                 (64 * QPITCH * 2 + 64 * VPITCH) * sizeof(__half)>>>(qs_h, ks_h, kv_h, attn_h);

    // output projection (fp16 tensor cores, fp32 out)
    hgemm<float><<<dim3(1024 / 128, T_ / 128), 256>>>(attn_h, wo_h, w_o_b, out,
                                                      T_, 1024, 2048);
}

// round 5
// speedup vs baseline: 8.9847x; 1.2433x over previous
#include <cuda_runtime.h>
#include <cuda_fp16.h>
#include <math.h>
#include <stdint.h>

#define B_   2
#define S_   2048
#define T_   4096      // B*S tokens
#define DIM_ 1024
#define H_   8

// ---------------- scratch (static device arrays; no allocs allowed) ----------
__device__ __half g_xcat[T_ * 3072];      // [x_hi | x_lo | x_hi] fp16
__device__ __half g_wdqkv[3072 * 384];    // stacked [Wdq|Wdkv] hi/hi/lo
__device__ float  g_bias_dqkv[384];
__device__ float  g_dqkv[T_ * 384];       // fused dq|dkv|kr output fp32
__device__ __half g_cqcat[T_ * 384];      // [cq_hi | cq_lo | cq_hi]
__device__ __half g_wuq[384 * 1024];      // stacked uq weights hi/hi/lo
__device__ float  g_q[T_ * 1024];         // up-projected q (pre-rope, fp32)
__device__ __half g_ckv_h[T_ * 128];      // normed kv latent (fp16)
__device__ __half g_krope_h[T_ * 64];     // roped k_rope (fp16)
__device__ __half g_kv_h[T_ * 2560];      // uk_uv output (k_nope | v) fp16
__device__ __half g_qs_h[16 * S_ * 128];  // q_states  [B*H, S, 128] fp16 (pre-scaled)
__device__ __half g_ks_h[16 * S_ * 128];  // k_states  [B*H, S, 128] fp16
__device__ __half g_attn_h[T_ * 2048];    // attn out  [token, h*256+c] fp16
__device__ __half g_wukuv_h[128 * 2560];
__device__ __half g_wo_h[2048 * 1024];

// ---------------- mma/ldmatrix/cp.async helpers ------------------------------
__device__ __forceinline__ uint32_t smem_u32(const void* p) {
    return (uint32_t)__cvta_generic_to_shared(p);
}
__device__ __forceinline__ void ldsm_x4(uint32_t* r, uint32_t addr) {
    asm volatile("ldmatrix.sync.aligned.m8n8.x4.shared.b16 {%0,%1,%2,%3},[%4];"
                 : "=r"(r[0]), "=r"(r[1]), "=r"(r[2]), "=r"(r[3]) : "r"(addr));
}
__device__ __forceinline__ void ldsm_x4_t(uint32_t* r, uint32_t addr) {
    asm volatile("ldmatrix.sync.aligned.m8n8.x4.trans.shared.b16 {%0,%1,%2,%3},[%4];"
                 : "=r"(r[0]), "=r"(r[1]), "=r"(r[2]), "=r"(r[3]) : "r"(addr));
}
__device__ __forceinline__ void mma16816(float* c, const uint32_t* a, const uint32_t* b) {
    asm volatile(
        "mma.sync.aligned.m16n8k16.row.col.f32.f16.f16.f32 "
        "{%0,%1,%2,%3},{%4,%5,%6,%7},{%8,%9},{%0,%1,%2,%3};"
        : "+f"(c[0]), "+f"(c[1]), "+f"(c[2]), "+f"(c[3])
        : "r"(a[0]), "r"(a[1]), "r"(a[2]), "r"(a[3]), "r"(b[0]), "r"(b[1]));
}
__device__ __forceinline__ uint32_t pack_h2(float lo, float hi) {
    __half2 h = __floats2half2_rn(lo, hi);
    return *(uint32_t*)&h;
}
__device__ __forceinline__ void cp16(void* smem_dst, const void* gsrc) {
    asm volatile("cp.async.cg.shared.global [%0],[%1],16;"
                 :: "r"(smem_u32(smem_dst)), "l"(gsrc));
}
#define CP_COMMIT() asm volatile("cp.async.commit_group;")
#define CP_WAIT(n)  asm volatile("cp.async.wait_group %0;" :: "n"(n))

// ---------------- prep kernels ------------------------------------------------
__global__ void f2h(const float* __restrict__ src, __half* __restrict__ dst, int n) {
    int i = blockIdx.x * blockDim.x + threadIdx.x;
    if (i < n) dst[i] = __float2half(src[i]);
}

// x -> [x_hi | x_lo | x_hi] per row (K 1024 -> 3072)
__global__ void split_x(const float* __restrict__ x, __half* __restrict__ xcat) {
    int i = blockIdx.x * blockDim.x + threadIdx.x;
    if (i >= T_ * 1024) return;
    int row = i >> 10, col = i & 1023;
    float v = x[i];
    __half hi = __float2half(v);
    __half lo = __float2half(v - __half2float(hi));
    __half* r = xcat + (size_t)row * 3072;
    r[col] = hi;
    r[1024 + col] = lo;
    r[2048 + col] = hi;
}

// stacked fused weight [3072 x 384]: cols [0,128)=Wdq, [128,320)=Wdkv, rest 0
// rows [0,1024)=hi, [1024,2048)=hi, [2048,3072)=lo
__global__ void prep_wdqkv(const float* __restrict__ wdq, const float* __restrict__ wdkv,
                           __half* __restrict__ wcat) {
    int i = blockIdx.x * blockDim.x + threadIdx.x;
    if (i >= 1024 * 384) return;
    int k = i / 384, j = i - k * 384;
    float v = (j < 128) ? wdq[k * 128 + j] : (j < 320 ? wdkv[k * 192 + (j - 128)] : 0.f);
    __half hi = __float2half(v);
    __half lo = __float2half(v - __half2float(hi));
    wcat[(size_t)k * 384 + j] = hi;
    wcat[(size_t)(1024 + k) * 384 + j] = hi;
    wcat[(size_t)(2048 + k) * 384 + j] = lo;
}

__global__ void prep_bias_dqkv(const float* __restrict__ bdq, const float* __restrict__ bdkv,
                               float* __restrict__ bias) {
    int j = threadIdx.x;
    bias[j] = (j < 128) ? bdq[j] : (j < 320 ? bdkv[j - 128] : 0.f);
}

// stacked uq weight [384 x 1024]: rows [0,128)=hi, [128,256)=hi, [256,384)=lo
__global__ void prep_wuq(const float* __restrict__ w, __half* __restrict__ wcat) {
    int i = blockIdx.x * blockDim.x + threadIdx.x;
    if (i >= 128 * 1024) return;
    int k = i >> 10, j = i & 1023;
    float v = w[i];
    __half hi = __float2half(v);
    __half lo = __float2half(v - __half2float(hi));
    wcat[(size_t)k * 1024 + j] = hi;
    wcat[(size_t)(128 + k) * 1024 + j] = hi;
    wcat[(size_t)(256 + k) * 1024 + j] = lo;
}

// ---------------- fp16 tensor-core GEMM (double-buffered cp.async) -----------
// BM=128 BN=128 BK=32, 256 threads (8 warps, 2x4), warp tile 64x32.
template <typename OutT>
__global__ __launch_bounds__(256, 2) void hgemm(
    const __half* __restrict__ A, const __half* __restrict__ Bm,
    const float* __restrict__ bias, OutT* __restrict__ C, int M, int N, int K) {
    __shared__ __half As[2][128][40];
    __shared__ __half Bs[2][32][136];

    int tid = threadIdx.x, lane = tid & 31, w = tid >> 5;
    int wr = w >> 2, wc = w & 3;
    int row0 = blockIdx.y * 128, col0 = blockIdx.x * 128;

    float acc[16][4];
    #pragma unroll
    for (int i = 0; i < 16; i++)
        #pragma unroll
        for (int j = 0; j < 4; j++) acc[i][j] = 0.f;

    int ar = tid >> 2, ac = (tid & 3) * 8;   // 128 rows, 4 cp per row... (2 iters)
    int br = tid >> 4, bc = (tid & 15) * 8;

    int nk = K >> 5;
    // prologue: stage 0
    {
        const __half* Ab = A + (size_t)row0 * K;
        #pragma unroll
        for (int it = 0; it < 2; it++) {
            int e = it * 256 + tid;
            int r = e >> 2, c = (e & 3) * 8;
            cp16(&As[0][r][c], Ab + (size_t)r * K + c);
        }
        #pragma unroll
        for (int it = 0; it < 2; it++) {
            int e = it * 256 + tid;
            int r = e >> 4, c = (e & 15) * 8;
            cp16(&Bs[0][r][c], Bm + (size_t)r * N + col0 + c);
        }
    }
    CP_COMMIT();

    for (int kt = 0; kt < nk; kt++) {
        int cur = kt & 1;
        if (kt + 1 < nk) {
            int k0 = (kt + 1) << 5;
            const __half* Ab = A + (size_t)row0 * K + k0;
            #pragma unroll
            for (int it = 0; it < 2; it++) {
                int e = it * 256 + tid;
                int r = e >> 2, c = (e & 3) * 8;
                cp16(&As[cur ^ 1][r][c], Ab + (size_t)r * K + c);
            }
            const __half* Bb = Bm + (size_t)k0 * N + col0;
            #pragma unroll
            for (int it = 0; it < 2; it++) {
                int e = it * 256 + tid;
                int r = e >> 4, c = (e & 15) * 8;
                cp16(&Bs[cur ^ 1][r][c], Bb + (size_t)r * N + c);
            }
        }
        CP_COMMIT();
        CP_WAIT(1);
        __syncthreads();

        #pragma unroll
        for (int kk = 0; kk < 2; kk++) {
            uint32_t af[4][4], bf[2][4];
            #pragma unroll
            for (int mt = 0; mt < 4; mt++) {
                int r = wr * 64 + mt * 16 + (lane & 15);
                int c = kk * 16 + ((lane >> 4) << 3);
                ldsm_x4(af[mt], smem_u32(&As[cur][r][c]));
            }
            #pragma unroll
            for (int nt2 = 0; nt2 < 2; nt2++) {
                int kr = kk * 16 + (lane & 7) + (lane & 8);
                int nc = wc * 32 + nt2 * 16 + ((lane >> 4) << 3);
                ldsm_x4_t(bf[nt2], smem_u32(&Bs[cur][kr][nc]));
            }
            #pragma unroll
            for (int mt = 0; mt < 4; mt++)
                #pragma unroll
                for (int nt = 0; nt < 4; nt++)
                    mma16816(acc[mt * 4 + nt], af[mt], bf[nt >> 1] + (nt & 1) * 2);
        }
        __syncthreads();
    }

    // epilogue
    #pragma unroll
    for (int mt = 0; mt < 4; mt++) {
        #pragma unroll
        for (int nt = 0; nt < 4; nt++) {
            int row = row0 + wr * 64 + mt * 16 + (lane >> 2);
            int col = col0 + wc * 32 + nt * 8 + (lane & 3) * 2;
            float b0 = bias[col], b1 = bias[col + 1];
            float v0 = acc[mt * 4 + nt][0] + b0;
            float v1 = acc[mt * 4 + nt][1] + b1;
            float v2 = acc[mt * 4 + nt][2] + b0;
            float v3 = acc[mt * 4 + nt][3] + b1;
            if (sizeof(OutT) == 2) {
                *(__half2*)((__half*)C + (size_t)row * N + col) = __floats2half2_rn(v0, v1);
                *(__half2*)((__half*)C + (size_t)(row + 8) * N + col) = __floats2half2_rn(v2, v3);
            } else {
                *(float2*)((float*)C + (size_t)row * N + col) = make_float2(v0, v1);
                *(float2*)((float*)C + (size_t)(row + 8) * N + col) = make_float2(v2, v3);
            }
        }
    }
}

// ---------------- fused post-dqkv: 2x rmsnorm + k-rope + hi/lo split ---------
__global__ void postproc(const float* __restrict__ dqkv, const int* __restrict__ pos,
                         const float* __restrict__ qnw, const float* __restrict__ kvnw,
                         __half* __restrict__ cqcat, __half* __restrict__ ckv,
                         __half* __restrict__ krope) {
    __shared__ float r1[128], r2[128];
    int t = blockIdx.x, d = threadIdx.x;
    const float* row = dqkv + (size_t)t * 384;
    float qv = row[d], kvv = row[128 + d];
    r1[d] = qv * qv;
    r2[d] = kvv * kvv;
    __syncthreads();
    #pragma unroll
    for (int s = 64; s > 0; s >>= 1) {
        if (d < s) { r1[d] += r1[d + s]; r2[d] += r2[d + s]; }
        __syncthreads();
    }
    float invq = rsqrtf(r1[0] * (1.f / 128.f) + 1e-8f);
    float invk = rsqrtf(r2[0] * (1.f / 128.f) + 1e-8f);
    float cq = qnw[d] * qv * invq;
    __half hi = __float2half(cq);
    __half lo = __float2half(cq - __half2float(hi));
    __half* cr = cqcat + (size_t)t * 384;
    cr[d] = hi;
    cr[128 + d] = lo;
    cr[256 + d] = hi;
    ckv[(size_t)t * 128 + d] = __float2half(kvnw[d] * kvv * invk);
    if (d < 32) {
        float p = (float)pos[t];
        float freq = powf(10000.f, -(float)(2 * d) / 64.f);
        float ang = p * freq;
        float c = cosf(ang), s = sinf(ang);
        float xe = row[256 + 2 * d], xo = row[256 + 2 * d + 1];
        krope[(size_t)t * 64 + 2 * d]     = __float2half(xe * c - xo * s);
        krope[(size_t)t * 64 + 2 * d + 1] = __float2half(xe * s + xo * c);
    }
}

// ---------------- build q_states (rope + pre-scale) fp16 ---------------------
#define SCALE_ 0.08838834764831845f
__global__ void build_q(const float* __restrict__ q, const int* __restrict__ pos_ids,
                        __half* __restrict__ qs) {
    int t = blockIdx.x;
    int d = threadIdx.x;
    int b = t >> 11, s = t & 2047;
    float pos = (float)pos_ids[t];
    #pragma unroll
    for (int h = 0; h < 8; h++) {
        float val;
        if (d < 96) {
            val = q[(size_t)t * 1024 + h * 96 + d];
        } else {
            int rr = d - 96;
            int i = rr >> 1;
            float freq = powf(10000.f, -(float)(2 * i) / 32.f);
            float ang = pos * freq;
            float c = cosf(ang), sn = sinf(ang);
            float xe = q[(size_t)t * 1024 + 768 + h * 32 + 2 * i];
            float xo = q[(size_t)t * 1024 + 768 + h * 32 + 2 * i + 1];
            val = (rr & 1) ? (xe * sn + xo * c) : (xe * c - xo * sn);
        }
        qs[(((size_t)(b * 8 + h)) * S_ + s) * 128 + d] = __float2half(val * SCALE_);
    }
}

__global__ void build_k(const __half* __restrict__ kv, const __half* __restrict__ krope,
                        __half* __restrict__ ks) {
    int t = blockIdx.x;
    int d = threadIdx.x;
    int b = t >> 11, s = t & 2047;
    __half kr;
    if (d >= 64) kr = krope[(size_t)t * 64 + (d - 64)];
    #pragma unroll
    for (int h = 0; h < 8; h++) {
        __half val = (d < 64) ? kv[(size_t)t * 2560 + h * 64 + d] : kr;
        ks[(((size_t)(b * 8 + h)) * S_ + s) * 128 + d] = val;
    }
}

// ---------------- fp16 flash attention, cp.async double-buffered -------------
#define QP 136
#define VP 264
// smem: Ks[2] 64x136 each, Vs[2] 64x264 each = 51200 halves = 100 KB.
// Q tile overlays Ks[0] during prologue.
__global__ __launch_bounds__(256, 1) void flash_fp16(
    const __half* __restrict__ Qg, const __half* __restrict__ Kg,
    const __half* __restrict__ KVg, __half* __restrict__ Og) {
    extern __shared__ __half sm[];
    __half* Ksm[2] = { sm, sm + 64 * QP };
    __half* Vsm[2] = { sm + 2 * 64 * QP, sm + 2 * 64 * QP + 64 * VP };

    int tid = threadIdx.x, lane = tid & 31, w = tid >> 5;
    int qr = w & 3, vh = w >> 2;
    int bh = blockIdx.y;
    int b = bh >> 3, h = bh & 7;
    int q0 = blockIdx.x * 64;

    // load Q tile into Ks[0] (async), pull fragments, then release the buffer
    {
        const __half* qbase = Qg + ((size_t)bh * S_ + q0) * 128;
        #pragma unroll
        for (int it = 0; it < 4; it++) {
            int e = it * 256 + tid;
            int r = e >> 4, c = (e & 15) * 8;
            cp16(&Ksm[0][r * QP + c], qbase + (size_t)r * 128 + c);
        }
    }
    CP_COMMIT();
    CP_WAIT(0);
    __syncthreads();

    uint32_t qf[8][4];
    #pragma unroll
    for (int ks = 0; ks < 8; ks++) {
        int r = qr * 16 + (lane & 15);
        int c = ks * 16 + ((lane >> 4) << 3);
        ldsm_x4(qf[ks], smem_u32(&Ksm[0][r * QP + c]));
    }
    __syncthreads();  // all warps done reading Q before stage-0 K overwrites

    const __half* kbase0 = Kg + (size_t)bh * S_ * 128;
    const __half* vbase0 = KVg + (size_t)(b * S_) * 2560 + 512 + h * 256;

    // prologue: stage 0 <- kb 0
    #pragma unroll
    for (int it = 0; it < 4; it++) {
        int e = it * 256 + tid;
        int r = e >> 4, c = (e & 15) * 8;
        cp16(&Ksm[0][r * QP + c], kbase0 + (size_t)r * 128 + c);
    }
    #pragma unroll
    for (int it = 0; it < 8; it++) {
        int e = it * 256 + tid;
        int r = e >> 5, c = (e & 31) * 8;
        cp16(&Vsm[0][r * VP + c], vbase0 + (size_t)r * 2560 + c);
    }
    CP_COMMIT();

    float m[2] = {-1e30f, -1e30f}, l[2] = {0.f, 0.f};
    float o[16][4];
    #pragma unroll
    for (int i = 0; i < 16; i++)
        #pragma unroll
        for (int j = 0; j < 4; j++) o[i][j] = 0.f;

    for (int kb = 0; kb < S_ / 64; kb++) {
        int cur = kb & 1;
        if (kb + 1 < S_ / 64) {
            const __half* kb2 = kbase0 + (size_t)(kb + 1) * 64 * 128;
            const __half* vb2 = vbase0 + (size_t)(kb + 1) * 64 * 2560;
            __half* Kd = Ksm[cur ^ 1];
            __half* Vd = Vsm[cur ^ 1];
            #pragma unroll
            for (int it = 0; it < 4; it++) {
                int e = it * 256 + tid;
                int r = e >> 4, c = (e & 15) * 8;
                cp16(&Kd[r * QP + c], kb2 + (size_t)r * 128 + c);
            }
            #pragma unroll
            for (int it = 0; it < 8; it++) {
                int e = it * 256 + tid;
                int r = e >> 5, c = (e & 31) * 8;
                cp16(&Vd[r * VP + c], vb2 + (size_t)r * 2560 + c);
            }
        }
        CP_COMMIT();
        CP_WAIT(1);
        __syncthreads();

        const __half* Ks = Ksm[cur];
        const __half* Vs = Vsm[cur];

        // S = Q @ K^T (16x64 per warp; Q pre-scaled)
        float s[8][4];
        #pragma unroll
        for (int i = 0; i < 8; i++)
            #pragma unroll
            for (int j = 0; j < 4; j++) s[i][j] = 0.f;
        #pragma unroll
        for (int ks = 0; ks < 8; ks++) {
            #pragma unroll
            for (int nt2 = 0; nt2 < 4; nt2++) {
                uint32_t bfr[4];
                int n = nt2 * 16 + ((lane >> 4) << 3) + (lane & 7);
                int k = ks * 16 + (lane & 8);
                ldsm_x4(bfr, smem_u32(&Ks[n * QP + k]));
                mma16816(s[2 * nt2],     qf[ks], bfr + 0);
                mma16816(s[2 * nt2 + 1], qf[ks], bfr + 2);
            }
        }

        // online softmax (rows: lane>>2 and +8)
        #pragma unroll
        for (int rr = 0; rr < 2; rr++) {
            float mx = -1e30f;
            #pragma unroll
            for (int j = 0; j < 8; j++)
                mx = fmaxf(mx, fmaxf(s[j][2 * rr], s[j][2 * rr + 1]));
            mx = fmaxf(mx, __shfl_xor_sync(0xffffffffu, mx, 1));
            mx = fmaxf(mx, __shfl_xor_sync(0xffffffffu, mx, 2));
            float m_new = fmaxf(m[rr], mx);
            float alpha = __expf(m[rr] - m_new);
            float tsum = 0.f;
            #pragma unroll
            for (int j = 0; j < 8; j++) {
                float p0 = __expf(s[j][2 * rr] - m_new);
                float p1 = __expf(s[j][2 * rr + 1] - m_new);
                s[j][2 * rr] = p0;
                s[j][2 * rr + 1] = p1;
                tsum += p0 + p1;
            }
            tsum += __shfl_xor_sync(0xffffffffu, tsum, 1);
            tsum += __shfl_xor_sync(0xffffffffu, tsum, 2);
            l[rr] = l[rr] * alpha + tsum;
            m[rr] = m_new;
            #pragma unroll
            for (int j = 0; j < 16; j++) {
                o[j][2 * rr] *= alpha;
                o[j][2 * rr + 1] *= alpha;
            }
        }

        // P fragments (fp16) from registers
        uint32_t pf[4][4];
        #pragma unroll
        for (int kk = 0; kk < 4; kk++) {
            pf[kk][0] = pack_h2(s[2 * kk][0],     s[2 * kk][1]);
            pf[kk][1] = pack_h2(s[2 * kk][2],     s[2 * kk][3]);
            pf[kk][2] = pack_h2(s[2 * kk + 1][0], s[2 * kk + 1][1]);
            pf[kk][3] = pack_h2(s[2 * kk + 1][2], s[2 * kk + 1][3]);
        }

        // O += P @ V (warp covers 128 V cols at vh*128)
        #pragma unroll
        for (int kk = 0; kk < 4; kk++) {
            #pragma unroll
            for (int nt2 = 0; nt2 < 8; nt2++) {
                uint32_t bfr[4];
                int k = kk * 16 + (lane & 7) + (lane & 8);
                int n = vh * 128 + nt2 * 16 + ((lane >> 4) << 3);
                ldsm_x4_t(bfr, smem_u32(&Vs[k * VP + n]));
                mma16816(o[2 * nt2],     pf[kk], bfr + 0);
                mma16816(o[2 * nt2 + 1], pf[kk], bfr + 2);
            }
        }
        __syncthreads();
    }

    // epilogue: write fp16 attn [token][h*256 + vh*128 + c]
    #pragma unroll
    for (int rr = 0; rr < 2; rr++) {
        float inv = 1.f / l[rr];
        int row = q0 + qr * 16 + (lane >> 2) + rr * 8;
        size_t base = ((size_t)(b * S_) + row) * 2048 + h * 256 + vh * 128;
        #pragma unroll
        for (int j = 0; j < 16; j++) {
            int c = j * 8 + (lane & 3) * 2;
            *(__half2*)&Og[base + c] =
                __floats2half2_rn(o[j][2 * rr] * inv, o[j][2 * rr + 1] * inv);
        }
    }
}

// ---------------- launch -----------------------------------------------------
extern "C" void kernel_launch(void* const* d_in, const int* in_sizes, int n_in,
                              void* d_out, int out_size) {
    const float* x        = (const float*)d_in[0];
    const int*   pos      = (const int*)d_in[1];
    const float* w_dq_w   = (const float*)d_in[2];
    const float* w_dq_b   = (const float*)d_in[3];
    const float* q_norm_w = (const float*)d_in[4];
    const float* w_uq_w   = (const float*)d_in[5];
    const float* w_uq_b   = (const float*)d_in[6];
    const float* w_dkv_w  = (const float*)d_in[7];
    const float* w_dkv_b  = (const float*)d_in[8];
    const float* kv_norm_w= (const float*)d_in[9];
    const float* w_ukuv_w = (const float*)d_in[10];
    const float* w_ukuv_b = (const float*)d_in[11];
    const float* w_o_w    = (const float*)d_in[12];
    const float* w_o_b    = (const float*)d_in[13];
    float* out = (float*)d_out;

    __half *xcat, *wdqkv, *cqcat, *wuq, *ckv_h, *krope_h, *kv_h, *qs_h, *ks_h, *attn_h,
           *wukuv_h, *wo_h;
    float *dqkv, *bias_dqkv, *q;
    cudaGetSymbolAddress((void**)&xcat,     g_xcat);
    cudaGetSymbolAddress((void**)&wdqkv,    g_wdqkv);
    cudaGetSymbolAddress((void**)&bias_dqkv,g_bias_dqkv);
    cudaGetSymbolAddress((void**)&dqkv,     g_dqkv);
    cudaGetSymbolAddress((void**)&cqcat,    g_cqcat);
    cudaGetSymbolAddress((void**)&wuq,      g_wuq);
    cudaGetSymbolAddress((void**)&q,        g_q);
    cudaGetSymbolAddress((void**)&ckv_h,    g_ckv_h);
    cudaGetSymbolAddress((void**)&krope_h,  g_krope_h);
    cudaGetSymbolAddress((void**)&kv_h,     g_kv_h);
    cudaGetSymbolAddress((void**)&qs_h,     g_qs_h);
    cudaGetSymbolAddress((void**)&ks_h,     g_ks_h);
    cudaGetSymbolAddress((void**)&attn_h,   g_attn_h);
    cudaGetSymbolAddress((void**)&wukuv_h,  g_wukuv_h);
    cudaGetSymbolAddress((void**)&wo_h,     g_wo_h);

    // prep
    split_x<<<(T_ * 1024 + 255) / 256, 256>>>(x, xcat);
    prep_wdqkv<<<(1024 * 384 + 255) / 256, 256>>>(w_dq_w, w_dkv_w, wdqkv);
    prep_bias_dqkv<<<1, 384>>>(w_dq_b, w_dkv_b, bias_dqkv);
    prep_wuq<<<(128 * 1024 + 255) / 256, 256>>>(w_uq_w, wuq);
    f2h<<<(128 * 2560 + 255) / 256, 256>>>(w_ukuv_w, wukuv_h, 128 * 2560);
    f2h<<<(2048 * 1024 + 255) / 256, 256>>>(w_o_w, wo_h, 2048 * 1024);

    // fused dq+dkv (split-fp16, K=3072)
    hgemm<float><<<dim3(3, T_ / 128), 256>>>(xcat, wdqkv, bias_dqkv, dqkv, T_, 384, 3072);
    // norms + k-rope + cq hi/lo split
    postproc<<<T_, 128>>>(dqkv, pos, q_norm_w, kv_norm_w, cqcat, ckv_h, krope_h);
    // uq (split-fp16, K=384)
    hgemm<float><<<dim3(8, T_ / 128), 256>>>(cqcat, wuq, w_uq_b, q, T_, 1024, 384);
    // kv = ckv @ w_ukuv + b
    hgemm<__half><<<dim3(20, T_ / 128), 256>>>(ckv_h, wukuv_h, w_ukuv_b, kv_h, T_, 2560, 128);

    // attention layouts
    build_q<<<T_, 128>>>(q, pos, qs_h);
    build_k<<<T_, 128>>>(kv_h, krope_h, ks_h);

    // flash attention
    int fsmem = (2 * 64 * QP + 2 * 64 * VP) * (int)sizeof(__half);  // 102400
    cudaFuncSetAttribute(flash_fp16, cudaFuncAttributeMaxDynamicSharedMemorySize, fsmem);
    flash_fp16<<<dim3(S_ / 64, 16), 256, fsmem>>>(qs_h, ks_h, kv_h, attn_h);

    // output projection
    hgemm<float><<<dim3(8, T_ / 128), 256>>>(attn_h, wo_h, w_o_b, out, T_, 1024, 2048);
}

// round 6
// speedup vs baseline: 9.6428x; 1.0732x over previous
#include <cuda_runtime.h>
#include <cuda_fp16.h>
#include <math.h>
#include <stdint.h>

#define B_   2
#define S_   2048
#define T_   4096      // B*S tokens
#define DIM_ 1024
#define SCALE_ 0.08838834764831845f   // 1/sqrt(128)

// ---------------- scratch (static device arrays) -----------------------------
__device__ __half g_xcat[T_ * 3072];       // [x_hi | x_lo | x_hi]
__device__ __half g_wdqkv[3072 * 384];     // stacked [Wdq|Wdkv] hi/hi/lo
__device__ float  g_bias_dqkv[384];
__device__ float  g_dqkv[T_ * 384];        // dq|dkv|kr fp32
__device__ __half g_cqcat[T_ * 384];       // [cq_hi | cq_lo | cq_hi]
__device__ __half g_wuqeff[384 * 1536];    // absorbed uq weights hi/hi/lo (scaled)
__device__ float  g_biaseff[1536];         // absorbed uq bias (scaled)
__device__ float  g_q32[T_ * 1536];        // q_eff pre-rope fp32
__device__ __half g_qe[16 * S_ * 192];     // q_eff [bh][s][192] fp16
__device__ __half g_keff[T_ * 192];        // [ckv_norm(128) | roped krope(64)] per token
__device__ __half g_attnlat[T_ * 1024];    // attn latent [t][h*128+c] fp16
__device__ __half g_wfA[8 * 128 * 768];    // Wfused GEMM A (split-K stacked)
__device__ __half g_wfB[8 * 768 * 1024];   // Wfused GEMM B
__device__ __half g_wfused[1024 * 1024];   // fused (W_uv @ W_o) fp16
__device__ float  g_boeff[1024];           // b_o + sum_h b_uv W_o
__device__ float  g_zb[1536];              // zero bias (never written)

// ---------------- mma/ldmatrix/cp.async helpers ------------------------------
__device__ __forceinline__ uint32_t smem_u32(const void* p) {
    return (uint32_t)__cvta_generic_to_shared(p);
}
__device__ __forceinline__ void ldsm_x4(uint32_t* r, uint32_t addr) {
    asm volatile("ldmatrix.sync.aligned.m8n8.x4.shared.b16 {%0,%1,%2,%3},[%4];"
                 : "=r"(r[0]), "=r"(r[1]), "=r"(r[2]), "=r"(r[3]) : "r"(addr));
}
__device__ __forceinline__ void ldsm_x4_t(uint32_t* r, uint32_t addr) {
    asm volatile("ldmatrix.sync.aligned.m8n8.x4.trans.shared.b16 {%0,%1,%2,%3},[%4];"
                 : "=r"(r[0]), "=r"(r[1]), "=r"(r[2]), "=r"(r[3]) : "r"(addr));
}
__device__ __forceinline__ void mma16816(float* c, const uint32_t* a, const uint32_t* b) {
    asm volatile(
        "mma.sync.aligned.m16n8k16.row.col.f32.f16.f16.f32 "
        "{%0,%1,%2,%3},{%4,%5,%6,%7},{%8,%9},{%0,%1,%2,%3};"
        : "+f"(c[0]), "+f"(c[1]), "+f"(c[2]), "+f"(c[3])
        : "r"(a[0]), "r"(a[1]), "r"(a[2]), "r"(a[3]), "r"(b[0]), "r"(b[1]));
}
__device__ __forceinline__ uint32_t pack_h2(float lo, float hi) {
    __half2 h = __floats2half2_rn(lo, hi);
    return *(uint32_t*)&h;
}
__device__ __forceinline__ void cp16(void* smem_dst, const void* gsrc) {
    asm volatile("cp.async.cg.shared.global [%0],[%1],16;"
                 :: "r"(smem_u32(smem_dst)), "l"(gsrc));
}
#define CP_COMMIT() asm volatile("cp.async.commit_group;")
#define CP_WAIT(n)  asm volatile("cp.async.wait_group %0;" :: "n"(n))

// ---------------- prep kernels ------------------------------------------------
// x -> [x_hi | x_lo | x_hi] (K 1024 -> 3072)
__global__ void split_x(const float* __restrict__ x, __half* __restrict__ xcat) {
    int i = blockIdx.x * blockDim.x + threadIdx.x;
    if (i >= T_ * 1024) return;
    int row = i >> 10, col = i & 1023;
    float v = x[i];
    __half hi = __float2half(v);
    __half lo = __float2half(v - __half2float(hi));
    __half* r = xcat + (size_t)row * 3072;
    r[col] = hi;
    r[1024 + col] = lo;
    r[2048 + col] = hi;
}

// stacked fused weight [3072 x 384]: cols [0,128)=Wdq, [128,320)=Wdkv, rest 0
__global__ void prep_wdqkv(const float* __restrict__ wdq, const float* __restrict__ wdkv,
                           __half* __restrict__ wcat) {
    int i = blockIdx.x * blockDim.x + threadIdx.x;
    if (i >= 1024 * 384) return;
    int k = i / 384, j = i - k * 384;
    float v = (j < 128) ? wdq[k * 128 + j] : (j < 320 ? wdkv[k * 192 + (j - 128)] : 0.f);
    __half hi = __float2half(v);
    __half lo = __float2half(v - __half2float(hi));
    wcat[(size_t)k * 384 + j] = hi;
    wcat[(size_t)(1024 + k) * 384 + j] = hi;
    wcat[(size_t)(2048 + k) * 384 + j] = lo;
}

__global__ void prep_bias_dqkv(const float* __restrict__ bdq, const float* __restrict__ bdkv,
                               float* __restrict__ bias) {
    int j = threadIdx.x;
    bias[j] = (j < 128) ? bdq[j] : (j < 320 ? bdkv[j - 128] : 0.f);
}

// absorbed uq weight: [128 cq-dims x 1536 (8 heads x 192)] -> stacked hi/hi/lo
// col h*192+c: c<128 latent (sum_j wuq[.,h*96+j]*wukuv[c,h*64+j]);
//             128<=c<160 nope passthrough; 160<=c<192 rope block. All x SCALE.
__global__ void prep_wuqeff(const float* __restrict__ wuq, const float* __restrict__ wukuv,
                            __half* __restrict__ wcat) {
    int i = blockIdx.x * blockDim.x + threadIdx.x;
    if (i >= 128 * 1536) return;
    int r = i / 1536, col = i - r * 1536;
    int h = col / 192, c = col - h * 192;
    float v;
    if (c < 128) {
        float s = 0.f;
        const float* wq = wuq + (size_t)r * 1024 + h * 96;
        const float* wk = wukuv + (size_t)c * 2560 + h * 64;
        #pragma unroll 16
        for (int j = 0; j < 64; j++) s += wq[j] * wk[j];
        v = s;
    } else if (c < 160) {
        v = wuq[(size_t)r * 1024 + h * 96 + 64 + (c - 128)];
    } else {
        v = wuq[(size_t)r * 1024 + 768 + h * 32 + (c - 160)];
    }
    v *= SCALE_;
    __half hi = __float2half(v);
    __half lo = __float2half(v - __half2float(hi));
    wcat[(size_t)r * 1536 + col] = hi;
    wcat[(size_t)(128 + r) * 1536 + col] = hi;
    wcat[(size_t)(256 + r) * 1536 + col] = lo;
}

__global__ void prep_biaseff(const float* __restrict__ buq, const float* __restrict__ wukuv,
                             float* __restrict__ be) {
    int col = blockIdx.x * blockDim.x + threadIdx.x;
    if (col >= 1536) return;
    int h = col / 192, c = col - h * 192;
    float v;
    if (c < 128) {
        float s = 0.f;
        const float* bq = buq + h * 96;
        const float* wk = wukuv + (size_t)c * 2560 + h * 64;
        for (int j = 0; j < 64; j++) s += bq[j] * wk[j];
        v = s;
    } else if (c < 160) {
        v = buq[h * 96 + 64 + (c - 128)];
    } else {
        v = buq[768 + h * 32 + (c - 160)];
    }
    be[col] = v * SCALE_;
}

// Wfused inputs: A[h][c][768] = [Wuv_hi | Wuv_lo | Wuv_hi] (Wuv[h]: ckv 128 x v 256)
__global__ void prep_wfA(const float* __restrict__ wukuv, __half* __restrict__ A) {
    int i = blockIdx.x * blockDim.x + threadIdx.x;
    if (i >= 8 * 128 * 256) return;
    int h = i >> 15, rem = i & 32767;
    int c = rem >> 8, v = rem & 255;
    float val = wukuv[(size_t)c * 2560 + 512 + h * 256 + v];
    __half hi = __float2half(val);
    __half lo = __float2half(val - __half2float(hi));
    __half* base = A + ((size_t)h * 128 + c) * 768;
    base[v] = hi;
    base[256 + v] = lo;
    base[512 + v] = hi;
}

// B[h][768][1024]: rows [W_o_hi | W_o_hi | W_o_lo] of w_o[h*256+v, :]
__global__ void prep_wfB(const float* __restrict__ wo, __half* __restrict__ Bm) {
    int i = blockIdx.x * blockDim.x + threadIdx.x;
    if (i >= 8 * 256 * 1024) return;
    int h = i >> 18, rem = i & 262143;
    int v = rem >> 10, o = rem & 1023;
    float val = wo[((size_t)h * 256 + v) * 1024 + o];
    __half hi = __float2half(val);
    __half lo = __float2half(val - __half2float(hi));
    __half* base = Bm + (size_t)h * 768 * 1024;
    base[(size_t)v * 1024 + o] = hi;
    base[(size_t)(256 + v) * 1024 + o] = hi;
    base[(size_t)(512 + v) * 1024 + o] = lo;
}

// bias_out_eff[o] = b_o[o] + sum_{r<2048} b_ukuv[512+r] * w_o[r, o]
__global__ void prep_boeff(const float* __restrict__ bo, const float* __restrict__ bukuv,
                           const float* __restrict__ wo, float* __restrict__ be) {
    int o = blockIdx.x * blockDim.x + threadIdx.x;
    if (o >= 1024) return;
    float s = bo[o];
    for (int r = 0; r < 2048; r++) s += bukuv[512 + r] * wo[(size_t)r * 1024 + o];
    be[o] = s;
}

// ---------------- fp16 tensor-core GEMM (double-buffered, batched-z) ---------
template <typename OutT>
__global__ __launch_bounds__(256, 2) void hgemm(
    const __half* __restrict__ A, const __half* __restrict__ Bm,
    const float* __restrict__ bias, OutT* __restrict__ C, int M, int N, int K,
    size_t zA, size_t zB, size_t zC) {
    __shared__ __half As[2][128][40];
    __shared__ __half Bs[2][32][136];

    A += blockIdx.z * zA;
    Bm += blockIdx.z * zB;
    C += blockIdx.z * zC;

    int tid = threadIdx.x, lane = tid & 31, w = tid >> 5;
    int wr = w >> 2, wc = w & 3;
    int row0 = blockIdx.y * 128, col0 = blockIdx.x * 128;

    float acc[16][4];
    #pragma unroll
    for (int i = 0; i < 16; i++)
        #pragma unroll
        for (int j = 0; j < 4; j++) acc[i][j] = 0.f;

    int nk = K >> 5;
    {
        const __half* Ab = A + (size_t)row0 * K;
        #pragma unroll
        for (int it = 0; it < 2; it++) {
            int e = it * 256 + tid;
            int r = e >> 2, c = (e & 3) * 8;
            cp16(&As[0][r][c], Ab + (size_t)r * K + c);
        }
        #pragma unroll
        for (int it = 0; it < 2; it++) {
            int e = it * 256 + tid;
            int r = e >> 4, c = (e & 15) * 8;
            cp16(&Bs[0][r][c], Bm + (size_t)r * N + col0 + c);
        }
    }
    CP_COMMIT();

    for (int kt = 0; kt < nk; kt++) {
        int cur = kt & 1;
        if (kt + 1 < nk) {
            int k0 = (kt + 1) << 5;
            const __half* Ab = A + (size_t)row0 * K + k0;
            #pragma unroll
            for (int it = 0; it < 2; it++) {
                int e = it * 256 + tid;
                int r = e >> 2, c = (e & 3) * 8;
                cp16(&As[cur ^ 1][r][c], Ab + (size_t)r * K + c);
            }
            const __half* Bb = Bm + (size_t)k0 * N + col0;
            #pragma unroll
            for (int it = 0; it < 2; it++) {
                int e = it * 256 + tid;
                int r = e >> 4, c = (e & 15) * 8;
                cp16(&Bs[cur ^ 1][r][c], Bb + (size_t)r * N + c);
            }
        }
        CP_COMMIT();
        CP_WAIT(1);
        __syncthreads();

        #pragma unroll
        for (int kk = 0; kk < 2; kk++) {
            uint32_t af[4][4], bf[2][4];
            #pragma unroll
            for (int mt = 0; mt < 4; mt++) {
                int r = wr * 64 + mt * 16 + (lane & 15);
                int c = kk * 16 + ((lane >> 4) << 3);
                ldsm_x4(af[mt], smem_u32(&As[cur][r][c]));
            }
            #pragma unroll
            for (int nt2 = 0; nt2 < 2; nt2++) {
                int kr = kk * 16 + (lane & 7) + (lane & 8);
                int nc = wc * 32 + nt2 * 16 + ((lane >> 4) << 3);
                ldsm_x4_t(bf[nt2], smem_u32(&Bs[cur][kr][nc]));
            }
            #pragma unroll
            for (int mt = 0; mt < 4; mt++)
                #pragma unroll
                for (int nt = 0; nt < 4; nt++)
                    mma16816(acc[mt * 4 + nt], af[mt], bf[nt >> 1] + (nt & 1) * 2);
        }
        __syncthreads();
    }

    #pragma unroll
    for (int mt = 0; mt < 4; mt++) {
        #pragma unroll
        for (int nt = 0; nt < 4; nt++) {
            int row = row0 + wr * 64 + mt * 16 + (lane >> 2);
            int col = col0 + wc * 32 + nt * 8 + (lane & 3) * 2;
            float b0 = bias[col], b1 = bias[col + 1];
            float v0 = acc[mt * 4 + nt][0] + b0;
            float v1 = acc[mt * 4 + nt][1] + b1;
            float v2 = acc[mt * 4 + nt][2] + b0;
            float v3 = acc[mt * 4 + nt][3] + b1;
            if (sizeof(OutT) == 2) {
                *(__half2*)((__half*)C + (size_t)row * N + col) = __floats2half2_rn(v0, v1);
                *(__half2*)((__half*)C + (size_t)(row + 8) * N + col) = __floats2half2_rn(v2, v3);
            } else {
                *(float2*)((float*)C + (size_t)row * N + col) = make_float2(v0, v1);
                *(float2*)((float*)C + (size_t)(row + 8) * N + col) = make_float2(v2, v3);
            }
        }
    }
}

// ---------------- fused post-dqkv: 2x rmsnorm + k-rope -> cqcat + keff -------
__global__ void postproc(const float* __restrict__ dqkv, const int* __restrict__ pos,
                         const float* __restrict__ qnw, const float* __restrict__ kvnw,
                         __half* __restrict__ cqcat, __half* __restrict__ keff) {
    __shared__ float r1[128], r2[128];
    int t = blockIdx.x, d = threadIdx.x;
    const float* row = dqkv + (size_t)t * 384;
    float qv = row[d], kvv = row[128 + d];
    r1[d] = qv * qv;
    r2[d] = kvv * kvv;
    __syncthreads();
    #pragma unroll
    for (int s = 64; s > 0; s >>= 1) {
        if (d < s) { r1[d] += r1[d + s]; r2[d] += r2[d + s]; }
        __syncthreads();
    }
    float invq = rsqrtf(r1[0] * (1.f / 128.f) + 1e-8f);
    float invk = rsqrtf(r2[0] * (1.f / 128.f) + 1e-8f);
    float cq = qnw[d] * qv * invq;
    __half hi = __float2half(cq);
    __half lo = __float2half(cq - __half2float(hi));
    __half* cr = cqcat + (size_t)t * 384;
    cr[d] = hi;
    cr[128 + d] = lo;
    cr[256 + d] = hi;
    keff[(size_t)t * 192 + d] = __float2half(kvnw[d] * kvv * invk);
    if (d < 32) {
        float p = (float)pos[t];
        float freq = powf(10000.f, -(float)(2 * d) / 64.f);
        float ang = p * freq;
        float c = cosf(ang), s = sinf(ang);
        float xe = row[256 + 2 * d], xo = row[256 + 2 * d + 1];
        keff[(size_t)t * 192 + 128 + 2 * d]     = __float2half(xe * c - xo * s);
        keff[(size_t)t * 192 + 128 + 2 * d + 1] = __float2half(xe * s + xo * c);
    }
}

// ---------------- build q_eff fp16 [bh][s][192] (rope last 32 of each 192) ---
__global__ void build_qeff(const float* __restrict__ q32, const int* __restrict__ pos,
                           __half* __restrict__ qe) {
    int t = blockIdx.x;
    int d = threadIdx.x;  // 0..191
    int b = t >> 11, s = t & 2047;
    float p = (float)pos[t];
    #pragma unroll
    for (int h = 0; h < 8; h++) {
        const float* row = q32 + (size_t)t * 1536 + h * 192;
        float val;
        if (d < 160) {
            val = row[d];
        } else {
            int i = (d - 160) >> 1;
            float freq = powf(10000.f, -(float)(2 * i) / 32.f);
            float ang = p * freq;
            float c = cosf(ang), sn = sinf(ang);
            float xe = row[160 + 2 * i], xo = row[161 + 2 * i];
            val = ((d - 160) & 1) ? (xe * sn + xo * c) : (xe * c - xo * sn);
        }
        qe[(((size_t)(b * 8 + h)) * S_ + s) * 192 + d] = __float2half(val);
    }
}

// ---------------- absorbed flash attention -----------------------------------
// grid (S/128, 16 bh), 256 threads (8 warps x 16 q rows). K_eff per batch is
// head-independent [b][s][192]; V = K_eff[:, 0:128]. Output attn_lat fp16.
#define KP 200   // smem row pitch (192+8): 400B rows, ldsm conflict-free
__global__ __launch_bounds__(256, 1) void flash_mla(
    const __half* __restrict__ Qe, const __half* __restrict__ Ke,
    __half* __restrict__ Out) {
    extern __shared__ __half sm[];   // 2 stages x 64 x KP = 128*KP halves (50 KB)

    int tid = threadIdx.x, lane = tid & 31, w = tid >> 5;
    int bh = blockIdx.y;
    int b = bh >> 3, h = bh & 7;
    int q0 = blockIdx.x * 128;

    // stage Q (128 x 192) through the full smem, pull fragments
    {
        const __half* qbase = Qe + ((size_t)bh * S_ + q0) * 192;
        #pragma unroll
        for (int it = 0; it < 12; it++) {
            int e = it * 256 + tid;          // 0..3071 (128 rows x 24 cp16)
            int r = e / 24, c = (e % 24) * 8;
            cp16(&sm[r * KP + c], qbase + (size_t)r * 192 + c);
        }
    }
    CP_COMMIT();
    CP_WAIT(0);
    __syncthreads();

    uint32_t qf[12][4];
    #pragma unroll
    for (int ks = 0; ks < 12; ks++) {
        int r = w * 16 + (lane & 15);
        int c = ks * 16 + ((lane >> 4) << 3);
        ldsm_x4(qf[ks], smem_u32(&sm[r * KP + c]));
    }
    __syncthreads();

    const __half* kbase = Ke + (size_t)b * S_ * 192;

    // prologue: tile 0 -> stage 0
    #pragma unroll
    for (int it = 0; it < 6; it++) {
        int e = it * 256 + tid;              // 0..1535 (64 rows x 24)
        int r = e / 24, c = (e % 24) * 8;
        cp16(&sm[r * KP + c], kbase + (size_t)r * 192 + c);
    }
    CP_COMMIT();

    float m[2] = {-1e30f, -1e30f}, l[2] = {0.f, 0.f};
    float o[16][4];
    #pragma unroll
    for (int i = 0; i < 16; i++)
        #pragma unroll
        for (int j = 0; j < 4; j++) o[i][j] = 0.f;

    for (int kb = 0; kb < S_ / 64; kb++) {
        int cur = kb & 1;
        if (kb + 1 < S_ / 64) {
            const __half* kb2 = kbase + (size_t)(kb + 1) * 64 * 192;
            __half* Kd = sm + (cur ^ 1) * 64 * KP;
            #pragma unroll
            for (int it = 0; it < 6; it++) {
                int e = it * 256 + tid;
                int r = e / 24, c = (e % 24) * 8;
                cp16(&Kd[r * KP + c], kb2 + (size_t)r * 192 + c);
            }
        }
        CP_COMMIT();
        CP_WAIT(1);
        __syncthreads();

        const __half* Ks = sm + cur * 64 * KP;

        // S = Qe @ Ke^T (16x64 per warp, 12 k-steps; pre-scaled)
        float s[8][4];
        #pragma unroll
        for (int i = 0; i < 8; i++)
            #pragma unroll
            for (int j = 0; j < 4; j++) s[i][j] = 0.f;
        #pragma unroll
        for (int ks = 0; ks < 12; ks++) {
            #pragma unroll
            for (int nt2 = 0; nt2 < 4; nt2++) {
                uint32_t bfr[4];
                int n = nt2 * 16 + ((lane >> 4) << 3) + (lane & 7);
                int k = ks * 16 + (lane & 8);
                ldsm_x4(bfr, smem_u32(&Ks[n * KP + k]));
                mma16816(s[2 * nt2],     qf[ks], bfr + 0);
                mma16816(s[2 * nt2 + 1], qf[ks], bfr + 2);
            }
        }

        // online softmax (rows: lane>>2 and +8)
        #pragma unroll
        for (int rr = 0; rr < 2; rr++) {
            float mx = -1e30f;
            #pragma unroll
            for (int j = 0; j < 8; j++)
                mx = fmaxf(mx, fmaxf(s[j][2 * rr], s[j][2 * rr + 1]));
            mx = fmaxf(mx, __shfl_xor_sync(0xffffffffu, mx, 1));
            mx = fmaxf(mx, __shfl_xor_sync(0xffffffffu, mx, 2));
            float m_new = fmaxf(m[rr], mx);
            float alpha = __expf(m[rr] - m_new);
            float tsum = 0.f;
            #pragma unroll
            for (int j = 0; j < 8; j++) {
                float p0 = __expf(s[j][2 * rr] - m_new);
                float p1 = __expf(s[j][2 * rr + 1] - m_new);
                s[j][2 * rr] = p0;
                s[j][2 * rr + 1] = p1;
                tsum += p0 + p1;
            }
            tsum += __shfl_xor_sync(0xffffffffu, tsum, 1);
            tsum += __shfl_xor_sync(0xffffffffu, tsum, 2);
            l[rr] = l[rr] * alpha + tsum;
            m[rr] = m_new;
            #pragma unroll
            for (int j = 0; j < 16; j++) {
                o[j][2 * rr] *= alpha;
                o[j][2 * rr + 1] *= alpha;
            }
        }

        uint32_t pf[4][4];
        #pragma unroll
        for (int kk = 0; kk < 4; kk++) {
            pf[kk][0] = pack_h2(s[2 * kk][0],     s[2 * kk][1]);
            pf[kk][1] = pack_h2(s[2 * kk][2],     s[2 * kk][3]);
            pf[kk][2] = pack_h2(s[2 * kk + 1][0], s[2 * kk + 1][1]);
            pf[kk][3] = pack_h2(s[2 * kk + 1][2], s[2 * kk + 1][3]);
        }

        // O += P @ V, V = Ks[:, 0:128]
        #pragma unroll
        for (int kk = 0; kk < 4; kk++) {
            #pragma unroll
            for (int nt2 = 0; nt2 < 8; nt2++) {
                uint32_t bfr[4];
                int k = kk * 16 + (lane & 7) + (lane & 8);
                int n = nt2 * 16 + ((lane >> 4) << 3);
                ldsm_x4_t(bfr, smem_u32(&Ks[k * KP + n]));
                mma16816(o[2 * nt2],     pf[kk], bfr + 0);
                mma16816(o[2 * nt2 + 1], pf[kk], bfr + 2);
            }
        }
        __syncthreads();
    }

    // epilogue: attn_lat[t][h*128 + c] fp16
    #pragma unroll
    for (int rr = 0; rr < 2; rr++) {
        float inv = 1.f / l[rr];
        int row = q0 + w * 16 + (lane >> 2) + rr * 8;
        size_t base = ((size_t)(b * S_) + row) * 1024 + h * 128;
        #pragma unroll
        for (int j = 0; j < 16; j++) {
            int c = j * 8 + (lane & 3) * 2;
            *(__half2*)&Out[base + c] =
                __floats2half2_rn(o[j][2 * rr] * inv, o[j][2 * rr + 1] * inv);
        }
    }
}

// ---------------- launch -----------------------------------------------------
extern "C" void kernel_launch(void* const* d_in, const int* in_sizes, int n_in,
                              void* d_out, int out_size) {
    const float* x        = (const float*)d_in[0];
    const int*   pos      = (const int*)d_in[1];
    const float* w_dq_w   = (const float*)d_in[2];
    const float* w_dq_b   = (const float*)d_in[3];
    const float* q_norm_w = (const float*)d_in[4];
    const float* w_uq_w   = (const float*)d_in[5];
    const float* w_uq_b   = (const float*)d_in[6];
    const float* w_dkv_w  = (const float*)d_in[7];
    const float* w_dkv_b  = (const float*)d_in[8];
    const float* kv_norm_w= (const float*)d_in[9];
    const float* w_ukuv_w = (const float*)d_in[10];
    const float* w_ukuv_b = (const float*)d_in[11];
    const float* w_o_w    = (const float*)d_in[12];
    const float* w_o_b    = (const float*)d_in[13];
    float* out = (float*)d_out;

    __half *xcat, *wdqkv, *cqcat, *wuqeff, *qe, *keff, *attnlat, *wfA, *wfB, *wfused;
    float *dqkv, *bias_dqkv, *biaseff, *q32, *boeff, *zb;
    cudaGetSymbolAddress((void**)&xcat,     g_xcat);
    cudaGetSymbolAddress((void**)&wdqkv,    g_wdqkv);
    cudaGetSymbolAddress((void**)&bias_dqkv,g_bias_dqkv);
    cudaGetSymbolAddress((void**)&dqkv,     g_dqkv);
    cudaGetSymbolAddress((void**)&cqcat,    g_cqcat);
    cudaGetSymbolAddress((void**)&wuqeff,   g_wuqeff);
    cudaGetSymbolAddress((void**)&biaseff,  g_biaseff);
    cudaGetSymbolAddress((void**)&q32,      g_q32);
    cudaGetSymbolAddress((void**)&qe,       g_qe);
    cudaGetSymbolAddress((void**)&keff,     g_keff);
    cudaGetSymbolAddress((void**)&attnlat,  g_attnlat);
    cudaGetSymbolAddress((void**)&wfA,      g_wfA);
    cudaGetSymbolAddress((void**)&wfB,      g_wfB);
    cudaGetSymbolAddress((void**)&wfused,   g_wfused);
    cudaGetSymbolAddress((void**)&boeff,    g_boeff);
    cudaGetSymbolAddress((void**)&zb,       g_zb);

    // ---- prep (independent) ----
    split_x<<<(T_ * 1024 + 255) / 256, 256>>>(x, xcat);
    prep_wdqkv<<<(1024 * 384 + 255) / 256, 256>>>(w_dq_w, w_dkv_w, wdqkv);
    prep_bias_dqkv<<<1, 384>>>(w_dq_b, w_dkv_b, bias_dqkv);
    prep_wuqeff<<<(128 * 1536 + 255) / 256, 256>>>(w_uq_w, w_ukuv_w, wuqeff);
    prep_biaseff<<<6, 256>>>(w_uq_b, w_ukuv_w, biaseff);
    prep_wfA<<<(8 * 128 * 256 + 255) / 256, 256>>>(w_ukuv_w, wfA);
    prep_wfB<<<(8 * 256 * 1024 + 255) / 256, 256>>>(w_o_w, wfB);
    prep_boeff<<<4, 256>>>(w_o_b, w_ukuv_b, w_o_w, boeff);

    // Wfused = W_uv @ W_o per head (split-fp16, batched over 8 heads)
    hgemm<__half><<<dim3(8, 1, 8), 256>>>(wfA, wfB, zb, wfused, 128, 1024, 768,
                                          (size_t)128 * 768, (size_t)768 * 1024,
                                          (size_t)128 * 1024);

    // ---- main path ----
    // fused dq+dkv (split-fp16, K=3072)
    hgemm<float><<<dim3(3, 32, 1), 256>>>(xcat, wdqkv, bias_dqkv, dqkv, T_, 384, 3072, 0, 0, 0);
    // norms + k-rope -> cqcat, keff
    postproc<<<T_, 128>>>(dqkv, pos, q_norm_w, kv_norm_w, cqcat, keff);
    // absorbed uq: q_eff pre-rope (split-fp16, K=384, N=1536)
    hgemm<float><<<dim3(12, 32, 1), 256>>>(cqcat, wuqeff, biaseff, q32, T_, 1536, 384, 0, 0, 0);
    // rope + fp16 layout
    build_qeff<<<T_, 192>>>(q32, pos, qe);

    // absorbed flash attention
    int fsmem = 128 * KP * (int)sizeof(__half);   // 51200
    cudaFuncSetAttribute(flash_mla, cudaFuncAttributeMaxDynamicSharedMemorySize, fsmem);
    flash_mla<<<dim3(S_ / 128, 16), 256, fsmem>>>(qe, keff, attnlat);

    // output projection: attn_lat @ Wfused + bo_eff
    hgemm<float><<<dim3(8, 32, 1), 256>>>(attnlat, wfused, boeff, out, T_, 1024, 1024, 0, 0, 0);
}

// round 9
// speedup vs baseline: 11.6587x; 1.2091x over previous
#include <cuda_runtime.h>
#include <cuda_fp16.h>
#include <math.h>
#include <stdint.h>

#define B_   2
#define S_   2048
#define T_   4096      // B*S tokens
#define DIM_ 1024
#define SCALE_ 0.08838834764831845f   // 1/sqrt(128)

// ---------------- scratch (static device arrays) -----------------------------
__device__ __half g_xcat[T_ * 3072];       // [x_hi | x_lo | x_hi]
__device__ __half g_wdqkv[3072 * 384];     // stacked [Wdq|Wdkv] hi/hi/lo
__device__ float  g_bias_dqkv[384];
__device__ float  g_dqkv[T_ * 384];        // split-K partial 0
__device__ float  g_dqkv2[T_ * 384];       // split-K partial 1
__device__ __half g_cqcat[T_ * 384];       // [cq_hi | cq_lo | cq_hi]
__device__ __half g_wuqeff[384 * 1536];    // absorbed uq weights hi/hi/lo (scaled)
__device__ float  g_biaseff[1536];         // absorbed uq bias (scaled)
__device__ __half g_qe[16 * S_ * 192];     // q_eff [bh][s][192] fp16
__device__ __half g_keff[T_ * 192];        // [ckv_norm(128) | roped krope(64)]
__device__ __half g_attnlat[T_ * 1024];    // attn latent [t][h*128+c] fp16
__device__ __half g_wfA[8 * 128 * 768];    // Wfused GEMM A (split-K stacked)
__device__ __half g_wfB[8 * 768 * 1024];   // Wfused GEMM B
__device__ __half g_wfused[1024 * 1024];   // fused (W_uv @ W_o) fp16
__device__ float  g_bopart[16 * 1024];     // boeff partials
__device__ float  g_boeff[1024];           // b_o + sum_h b_uv W_o
__device__ float  g_zb[1536];              // zero bias (never written)

// ---------------- mma/ldmatrix/cp.async helpers ------------------------------
__device__ __forceinline__ uint32_t smem_u32(const void* p) {
    return (uint32_t)__cvta_generic_to_shared(p);
}
__device__ __forceinline__ void ldsm_x4(uint32_t* r, uint32_t addr) {
    asm volatile("ldmatrix.sync.aligned.m8n8.x4.shared.b16 {%0,%1,%2,%3},[%4];"
                 : "=r"(r[0]), "=r"(r[1]), "=r"(r[2]), "=r"(r[3]) : "r"(addr));
}
__device__ __forceinline__ void ldsm_x4_t(uint32_t* r, uint32_t addr) {
    asm volatile("ldmatrix.sync.aligned.m8n8.x4.trans.shared.b16 {%0,%1,%2,%3},[%4];"
                 : "=r"(r[0]), "=r"(r[1]), "=r"(r[2]), "=r"(r[3]) : "r"(addr));
}
__device__ __forceinline__ void mma16816(float* c, const uint32_t* a, const uint32_t* b) {
    asm volatile(
        "mma.sync.aligned.m16n8k16.row.col.f32.f16.f16.f32 "
        "{%0,%1,%2,%3},{%4,%5,%6,%7},{%8,%9},{%0,%1,%2,%3};"
        : "+f"(c[0]), "+f"(c[1]), "+f"(c[2]), "+f"(c[3])
        : "r"(a[0]), "r"(a[1]), "r"(a[2]), "r"(a[3]), "r"(b[0]), "r"(b[1]));
}
__device__ __forceinline__ uint32_t pack_h2(float lo, float hi) {
    __half2 h = __floats2half2_rn(lo, hi);
    return *(uint32_t*)&h;
}
__device__ __forceinline__ void cp16(void* smem_dst, const void* gsrc) {
    asm volatile("cp.async.cg.shared.global [%0],[%1],16;"
                 :: "r"(smem_u32(smem_dst)), "l"(gsrc));
}
#define CP_COMMIT() asm volatile("cp.async.commit_group;")
#define CP_WAIT(n)  asm volatile("cp.async.wait_group %0;" :: "n"(n))

// ---------------- prep kernels ------------------------------------------------
// x -> [x_hi | x_lo | x_hi] (K 1024 -> 3072)
__global__ void split_x(const float* __restrict__ x, __half* __restrict__ xcat) {
    int i = blockIdx.x * blockDim.x + threadIdx.x;
    if (i >= T_ * 1024) return;
    int row = i >> 10, col = i & 1023;
    float v = x[i];
    __half hi = __float2half(v);
    __half lo = __float2half(v - __half2float(hi));
    __half* r = xcat + (size_t)row * 3072;
    r[col] = hi;
    r[1024 + col] = lo;
    r[2048 + col] = hi;
}

// stacked fused weight [3072 x 384]: cols [0,128)=Wdq, [128,320)=Wdkv, rest 0
__global__ void prep_wdqkv(const float* __restrict__ wdq, const float* __restrict__ wdkv,
                           __half* __restrict__ wcat) {
    int i = blockIdx.x * blockDim.x + threadIdx.x;
    if (i >= 1024 * 384) return;
    int k = i / 384, j = i - k * 384;
    float v = (j < 128) ? wdq[k * 128 + j] : (j < 320 ? wdkv[k * 192 + (j - 128)] : 0.f);
    __half hi = __float2half(v);
    __half lo = __float2half(v - __half2float(hi));
    wcat[(size_t)k * 384 + j] = hi;
    wcat[(size_t)(1024 + k) * 384 + j] = hi;
    wcat[(size_t)(2048 + k) * 384 + j] = lo;
}

__global__ void prep_bias_dqkv(const float* __restrict__ bdq, const float* __restrict__ bdkv,
                               float* __restrict__ bias) {
    int j = threadIdx.x;
    bias[j] = (j < 128) ? bdq[j] : (j < 320 ? bdkv[j - 128] : 0.f);
}

// absorbed latent block of Wuq_eff via smem-tiled per-head GEMM:
// out[r, h*192+c] = SCALE * sum_j wuq[r, h*96+j] * wukuv[c, h*64+j], c<128
__global__ void prep_wuqeff_gemm(const float* __restrict__ wuq,
                                 const float* __restrict__ wukuv,
                                 __half* __restrict__ wcat) {
    extern __shared__ float smf[];
    float (*Aq)[65] = (float(*)[65])smf;              // 128 x 65
    float (*Bk)[65] = (float(*)[65])(smf + 128 * 65); // 128 x 65
    int h = blockIdx.x;
    int tid = threadIdx.x;
    #pragma unroll
    for (int it = 0; it < 32; it++) {
        int e = it * 256 + tid;     // 0..8191
        int r = e >> 6, j = e & 63;
        Aq[r][j] = wuq[(size_t)r * 1024 + h * 96 + j];
        Bk[r][j] = wukuv[(size_t)r * 2560 + h * 64 + j];
    }
    __syncthreads();
    int ty = tid >> 4, tx = tid & 15;
    float acc[8][8];
    #pragma unroll
    for (int i = 0; i < 8; i++)
        #pragma unroll
        for (int k = 0; k < 8; k++) acc[i][k] = 0.f;
    for (int j = 0; j < 64; j++) {
        float a[8], bb[8];
        #pragma unroll
        for (int i = 0; i < 8; i++) { a[i] = Aq[ty * 8 + i][j]; bb[i] = Bk[tx * 8 + i][j]; }
        #pragma unroll
        for (int i = 0; i < 8; i++)
            #pragma unroll
            for (int k = 0; k < 8; k++) acc[i][k] += a[i] * bb[k];
    }
    #pragma unroll
    for (int i = 0; i < 8; i++) {
        #pragma unroll
        for (int k = 0; k < 8; k++) {
            float v = acc[i][k] * SCALE_;
            __half hi = __float2half(v);
            __half lo = __float2half(v - __half2float(hi));
            int r = ty * 8 + i;
            int col = h * 192 + tx * 8 + k;
            wcat[(size_t)r * 1536 + col] = hi;
            wcat[(size_t)(128 + r) * 1536 + col] = hi;
            wcat[(size_t)(256 + r) * 1536 + col] = lo;
        }
    }
}

// passthrough cols c in [128,192): nope tail + rope block
__global__ void prep_wuqeff_pass(const float* __restrict__ wuq, __half* __restrict__ wcat) {
    int i = blockIdx.x * blockDim.x + threadIdx.x;
    if (i >= 128 * 512) return;
    int r = i >> 9, rem = i & 511;
    int h = rem >> 6, cc = rem & 63;
    float v = (cc < 32) ? wuq[(size_t)r * 1024 + h * 96 + 64 + cc]
                        : wuq[(size_t)r * 1024 + 768 + h * 32 + (cc - 32)];
    v *= SCALE_;
    __half hi = __float2half(v);
    __half lo = __float2half(v - __half2float(hi));
    int col = h * 192 + 128 + cc;
    wcat[(size_t)r * 1536 + col] = hi;
    wcat[(size_t)(128 + r) * 1536 + col] = hi;
    wcat[(size_t)(256 + r) * 1536 + col] = lo;
}

__global__ void prep_biaseff(const float* __restrict__ buq, const float* __restrict__ wukuv,
                             float* __restrict__ be) {
    int col = blockIdx.x * blockDim.x + threadIdx.x;
    if (col >= 1536) return;
    int h = col / 192, c = col - h * 192;
    float v;
    if (c < 128) {
        float s = 0.f;
        const float* bq = buq + h * 96;
        const float* wk = wukuv + (size_t)c * 2560 + h * 64;
        for (int j = 0; j < 64; j++) s += bq[j] * wk[j];
        v = s;
    } else if (c < 160) {
        v = buq[h * 96 + 64 + (c - 128)];
    } else {
        v = buq[768 + h * 32 + (c - 160)];
    }
    be[col] = v * SCALE_;
}

// Wfused inputs: A[h][c][768] = [Wuv_hi | Wuv_lo | Wuv_hi]
__global__ void prep_wfA(const float* __restrict__ wukuv, __half* __restrict__ A) {
    int i = blockIdx.x * blockDim.x + threadIdx.x;
    if (i >= 8 * 128 * 256) return;
    int h = i >> 15, rem = i & 32767;
    int c = rem >> 8, v = rem & 255;
    float val = wukuv[(size_t)c * 2560 + 512 + h * 256 + v];
    __half hi = __float2half(val);
    __half lo = __float2half(val - __half2float(hi));
    __half* base = A + ((size_t)h * 128 + c) * 768;
    base[v] = hi;
    base[256 + v] = lo;
    base[512 + v] = hi;
}

// B[h][768][1024]: rows [W_o_hi | W_o_hi | W_o_lo]
__global__ void prep_wfB(const float* __restrict__ wo, __half* __restrict__ Bm) {
    int i = blockIdx.x * blockDim.x + threadIdx.x;
    if (i >= 8 * 256 * 1024) return;
    int h = i >> 18, rem = i & 262143;
    int v = rem >> 10, o = rem & 1023;
    float val = wo[((size_t)h * 256 + v) * 1024 + o];
    __half hi = __float2half(val);
    __half lo = __float2half(val - __half2float(hi));
    __half* base = Bm + (size_t)h * 768 * 1024;
    base[(size_t)v * 1024 + o] = hi;
    base[(size_t)(256 + v) * 1024 + o] = hi;
    base[(size_t)(512 + v) * 1024 + o] = lo;
}

// boeff phase 1: partial[z][o] = sum_{r in z*128..} bukuv[512+r] * wo[r, o]
__global__ void prep_boeff1(const float* __restrict__ bukuv, const float* __restrict__ wo,
                            float* __restrict__ part) {
    int o = blockIdx.x * 256 + threadIdx.x;
    int z = blockIdx.y;
    float s = 0.f;
    #pragma unroll 8
    for (int r = z * 128; r < (z + 1) * 128; r++)
        s += bukuv[512 + r] * wo[(size_t)r * 1024 + o];
    part[(size_t)z * 1024 + o] = s;
}
__global__ void prep_boeff2(const float* __restrict__ bo, const float* __restrict__ part,
                            float* __restrict__ be) {
    int o = blockIdx.x * 256 + threadIdx.x;
    float s = bo[o];
    #pragma unroll
    for (int z = 0; z < 16; z++) s += part[(size_t)z * 1024 + o];
    be[o] = s;
}

// ---------------- fp16 tensor-core GEMM (double-buffered, batched-z) ---------
// MODE 0: float out. MODE 1: half out. MODE 2: half out in qe layout with rope.
template <int MODE>
__global__ __launch_bounds__(256, 2) void hgemm(
    const __half* __restrict__ A, const __half* __restrict__ Bm,
    const float* __restrict__ bias, void* __restrict__ Cv, int M, int N, int K,
    int lda, size_t zA, size_t zB, size_t zC, const int* __restrict__ pos) {
    __shared__ __half As[2][128][40];
    __shared__ __half Bs[2][32][136];

    A += blockIdx.z * zA;
    Bm += blockIdx.z * zB;

    int tid = threadIdx.x, lane = tid & 31, w = tid >> 5;
    int wr = w >> 2, wc = w & 3;
    int row0 = blockIdx.y * 128, col0 = blockIdx.x * 128;

    float acc[16][4];
    #pragma unroll
    for (int i = 0; i < 16; i++)
        #pragma unroll
        for (int j = 0; j < 4; j++) acc[i][j] = 0.f;

    int nk = K >> 5;
    {
        const __half* Ab = A + (size_t)row0 * lda;
        #pragma unroll
        for (int it = 0; it < 2; it++) {
            int e = it * 256 + tid;
            int r = e >> 2, c = (e & 3) * 8;
            cp16(&As[0][r][c], Ab + (size_t)r * lda + c);
        }
        #pragma unroll
        for (int it = 0; it < 2; it++) {
            int e = it * 256 + tid;
            int r = e >> 4, c = (e & 15) * 8;
            cp16(&Bs[0][r][c], Bm + (size_t)r * N + col0 + c);
        }
    }
    CP_COMMIT();

    for (int kt = 0; kt < nk; kt++) {
        int cur = kt & 1;
        if (kt + 1 < nk) {
            int k0 = (kt + 1) << 5;
            const __half* Ab = A + (size_t)row0 * lda + k0;
            #pragma unroll
            for (int it = 0; it < 2; it++) {
                int e = it * 256 + tid;
                int r = e >> 2, c = (e & 3) * 8;
                cp16(&As[cur ^ 1][r][c], Ab + (size_t)r * lda + c);
            }
            const __half* Bb = Bm + (size_t)k0 * N + col0;
            #pragma unroll
            for (int it = 0; it < 2; it++) {
                int e = it * 256 + tid;
                int r = e >> 4, c = (e & 15) * 8;
                cp16(&Bs[cur ^ 1][r][c], Bb + (size_t)r * N + c);
            }
        }
        CP_COMMIT();
        CP_WAIT(1);
        __syncthreads();

        #pragma unroll
        for (int kk = 0; kk < 2; kk++) {
            uint32_t af[4][4], bf[2][4];
            #pragma unroll
            for (int mt = 0; mt < 4; mt++) {
                int r = wr * 64 + mt * 16 + (lane & 15);
                int c = kk * 16 + ((lane >> 4) << 3);
                ldsm_x4(af[mt], smem_u32(&As[cur][r][c]));
            }
            #pragma unroll
            for (int nt2 = 0; nt2 < 2; nt2++) {
                int kr = kk * 16 + (lane & 7) + (lane & 8);
                int nc = wc * 32 + nt2 * 16 + ((lane >> 4) << 3);
                ldsm_x4_t(bf[nt2], smem_u32(&Bs[cur][kr][nc]));
            }
            #pragma unroll
            for (int mt = 0; mt < 4; mt++)
                #pragma unroll
                for (int nt = 0; nt < 4; nt++)
                    mma16816(acc[mt * 4 + nt], af[mt], bf[nt >> 1] + (nt & 1) * 2);
        }
        __syncthreads();
    }

    #pragma unroll
    for (int mt = 0; mt < 4; mt++) {
        #pragma unroll
        for (int nt = 0; nt < 4; nt++) {
            int row = row0 + wr * 64 + mt * 16 + (lane >> 2);
            int col = col0 + wc * 32 + nt * 8 + (lane & 3) * 2;
            float b0 = bias[col], b1 = bias[col + 1];
            float v0 = acc[mt * 4 + nt][0] + b0;
            float v1 = acc[mt * 4 + nt][1] + b1;
            float v2 = acc[mt * 4 + nt][2] + b0;
            float v3 = acc[mt * 4 + nt][3] + b1;
            if (MODE == 0) {
                float* C = (float*)Cv + blockIdx.z * zC;
                *(float2*)(C + (size_t)row * N + col) = make_float2(v0, v1);
                *(float2*)(C + (size_t)(row + 8) * N + col) = make_float2(v2, v3);
            } else if (MODE == 1) {
                __half* C = (__half*)Cv + blockIdx.z * zC;
                *(__half2*)(C + (size_t)row * N + col) = __floats2half2_rn(v0, v1);
                *(__half2*)(C + (size_t)(row + 8) * N + col) = __floats2half2_rn(v2, v3);
            } else {
                // qe layout: [bh][s][192], rope on cols c>=160 (pairs in-thread)
                __half* C = (__half*)Cv;
                int h = col / 192, c = col - h * 192;
                if (c >= 160) {
                    int i2 = (c - 160) >> 1;
                    float freq = powf(10000.f, -(float)(2 * i2) / 32.f);
                    float p0f = (float)pos[row], p1f = (float)pos[row + 8];
                    float a0 = p0f * freq, a1 = p1f * freq;
                    float c0 = cosf(a0), s0 = sinf(a0);
                    float c1 = cosf(a1), s1 = sinf(a1);
                    float t0 = v0 * c0 - v1 * s0, t1 = v0 * s0 + v1 * c0;
                    v0 = t0; v1 = t1;
                    t0 = v2 * c1 - v3 * s1; t1 = v2 * s1 + v3 * c1;
                    v2 = t0; v3 = t1;
                }
                int b = row >> 11, s = row & 2047;
                *(__half2*)(C + (((size_t)(b * 8 + h)) * S_ + s) * 192 + c) =
                    __floats2half2_rn(v0, v1);
                int row2 = row + 8;
                b = row2 >> 11; s = row2 & 2047;
                *(__half2*)(C + (((size_t)(b * 8 + h)) * S_ + s) * 192 + c) =
                    __floats2half2_rn(v2, v3);
            }
        }
    }
}

// ---------------- fused post-dqkv: sum split-K + 2x rmsnorm + k-rope ---------
__global__ void postproc(const float* __restrict__ dqkvA, const float* __restrict__ dqkvB,
                         const int* __restrict__ pos,
                         const float* __restrict__ qnw, const float* __restrict__ kvnw,
                         __half* __restrict__ cqcat, __half* __restrict__ keff) {
    __shared__ float r1[128], r2[128];
    int t = blockIdx.x, d = threadIdx.x;
    const float* rowA = dqkvA + (size_t)t * 384;
    const float* rowB = dqkvB + (size_t)t * 384;
    float qv = rowA[d] + rowB[d];
    float kvv = rowA[128 + d] + rowB[128 + d];
    r1[d] = qv * qv;
    r2[d] = kvv * kvv;
    __syncthreads();
    #pragma unroll
    for (int s = 64; s > 0; s >>= 1) {
        if (d < s) { r1[d] += r1[d + s]; r2[d] += r2[d + s]; }
        __syncthreads();
    }
    float invq = rsqrtf(r1[0] * (1.f / 128.f) + 1e-8f);
    float invk = rsqrtf(r2[0] * (1.f / 128.f) + 1e-8f);
    float cq = qnw[d] * qv * invq;
    __half hi = __float2half(cq);
    __half lo = __float2half(cq - __half2float(hi));
    __half* cr = cqcat + (size_t)t * 384;
    cr[d] = hi;
    cr[128 + d] = lo;
    cr[256 + d] = hi;
    keff[(size_t)t * 192 + d] = __float2half(kvnw[d] * kvv * invk);
    if (d < 32) {
        float p = (float)pos[t];
        float freq = powf(10000.f, -(float)(2 * d) / 64.f);
        float ang = p * freq;
        float c = cosf(ang), s = sinf(ang);
        float xe = rowA[256 + 2 * d] + rowB[256 + 2 * d];
        float xo = rowA[256 + 2 * d + 1] + rowB[256 + 2 * d + 1];
        keff[(size_t)t * 192 + 128 + 2 * d]     = __float2half(xe * c - xo * s);
        keff[(size_t)t * 192 + 128 + 2 * d + 1] = __float2half(xe * s + xo * c);
    }
}

// ---------------- absorbed flash attention -----------------------------------
// grid (S/128, 16 bh), 256 threads (8 warps x 16 q rows). K_eff per batch is
// head-independent [b][s][192]; V = K_eff[:, 0:128]. Output attn_lat fp16.
#define KP 200
__global__ __launch_bounds__(256, 1) void flash_mla(
    const __half* __restrict__ Qe, const __half* __restrict__ Ke,
    __half* __restrict__ Out) {
    extern __shared__ __half sm[];   // 2 stages x 64 x KP (50 KB)

    int tid = threadIdx.x, lane = tid & 31, w = tid >> 5;
    int bh = blockIdx.y;
    int b = bh >> 3, h = bh & 7;
    int q0 = blockIdx.x * 128;

    {
        const __half* qbase = Qe + ((size_t)bh * S_ + q0) * 192;
        #pragma unroll
        for (int it = 0; it < 12; it++) {
            int e = it * 256 + tid;
            int r = e / 24, c = (e % 24) * 8;
            cp16(&sm[r * KP + c], qbase + (size_t)r * 192 + c);
        }
    }
    CP_COMMIT();
    CP_WAIT(0);
    __syncthreads();

    uint32_t qf[12][4];
    #pragma unroll
    for (int ks = 0; ks < 12; ks++) {
        int r = w * 16 + (lane & 15);
        int c = ks * 16 + ((lane >> 4) << 3);
        ldsm_x4(qf[ks], smem_u32(&sm[r * KP + c]));
    }
    __syncthreads();

    const __half* kbase = Ke + (size_t)b * S_ * 192;

    #pragma unroll
    for (int it = 0; it < 6; it++) {
        int e = it * 256 + tid;
        int r = e / 24, c = (e % 24) * 8;
        cp16(&sm[r * KP + c], kbase + (size_t)r * 192 + c);
    }
    CP_COMMIT();

    float m[2] = {-1e30f, -1e30f}, l[2] = {0.f, 0.f};
    float o[16][4];
    #pragma unroll
    for (int i = 0; i < 16; i++)
        #pragma unroll
        for (int j = 0; j < 4; j++) o[i][j] = 0.f;

    for (int kb = 0; kb < S_ / 64; kb++) {
        int cur = kb & 1;
        if (kb + 1 < S_ / 64) {
            const __half* kb2 = kbase + (size_t)(kb + 1) * 64 * 192;
            __half* Kd = sm + (cur ^ 1) * 64 * KP;
            #pragma unroll
            for (int it = 0; it < 6; it++) {
                int e = it * 256 + tid;
                int r = e / 24, c = (e % 24) * 8;
                cp16(&Kd[r * KP + c], kb2 + (size_t)r * 192 + c);
            }
        }
        CP_COMMIT();
        CP_WAIT(1);
        __syncthreads();

        const __half* Ks = sm + cur * 64 * KP;

        float s[8][4];
        #pragma unroll
        for (int i = 0; i < 8; i++)
            #pragma unroll
            for (int j = 0; j < 4; j++) s[i][j] = 0.f;
        #pragma unroll
        for (int ks = 0; ks < 12; ks++) {
            #pragma unroll
            for (int nt2 = 0; nt2 < 4; nt2++) {
                uint32_t bfr[4];
                int n = nt2 * 16 + ((lane >> 4) << 3) + (lane & 7);
                int k = ks * 16 + (lane & 8);
                ldsm_x4(bfr, smem_u32(&Ks[n * KP + k]));
                mma16816(s[2 * nt2],     qf[ks], bfr + 0);
                mma16816(s[2 * nt2 + 1], qf[ks], bfr + 2);
            }
        }

        #pragma unroll
        for (int rr = 0; rr < 2; rr++) {
            float mx = -1e30f;
            #pragma unroll
            for (int j = 0; j < 8; j++)
                mx = fmaxf(mx, fmaxf(s[j][2 * rr], s[j][2 * rr + 1]));
            mx = fmaxf(mx, __shfl_xor_sync(0xffffffffu, mx, 1));
            mx = fmaxf(mx, __shfl_xor_sync(0xffffffffu, mx, 2));
            float m_new = fmaxf(m[rr], mx);
            float alpha = __expf(m[rr] - m_new);
            float tsum = 0.f;
            #pragma unroll
            for (int j = 0; j < 8; j++) {
                float p0 = __expf(s[j][2 * rr] - m_new);
                float p1 = __expf(s[j][2 * rr + 1] - m_new);
                s[j][2 * rr] = p0;
                s[j][2 * rr + 1] = p1;
                tsum += p0 + p1;
            }
            tsum += __shfl_xor_sync(0xffffffffu, tsum, 1);
            tsum += __shfl_xor_sync(0xffffffffu, tsum, 2);
            l[rr] = l[rr] * alpha + tsum;
            m[rr] = m_new;
            #pragma unroll
            for (int j = 0; j < 16; j++) {
                o[j][2 * rr] *= alpha;
                o[j][2 * rr + 1] *= alpha;
            }
        }

        uint32_t pf[4][4];
        #pragma unroll
        for (int kk = 0; kk < 4; kk++) {
            pf[kk][0] = pack_h2(s[2 * kk][0],     s[2 * kk][1]);
            pf[kk][1] = pack_h2(s[2 * kk][2],     s[2 * kk][3]);
            pf[kk][2] = pack_h2(s[2 * kk + 1][0], s[2 * kk + 1][1]);
            pf[kk][3] = pack_h2(s[2 * kk + 1][2], s[2 * kk + 1][3]);
        }

        #pragma unroll
        for (int kk = 0; kk < 4; kk++) {
            #pragma unroll
            for (int nt2 = 0; nt2 < 8; nt2++) {
                uint32_t bfr[4];
                int k = kk * 16 + (lane & 7) + (lane & 8);
                int n = nt2 * 16 + ((lane >> 4) << 3);
                ldsm_x4_t(bfr, smem_u32(&Ks[k * KP + n]));
                mma16816(o[2 * nt2],     pf[kk], bfr + 0);
                mma16816(o[2 * nt2 + 1], pf[kk], bfr + 2);
            }
        }
        __syncthreads();
    }

    #pragma unroll
    for (int rr = 0; rr < 2; rr++) {
        float inv = 1.f / l[rr];
        int row = q0 + w * 16 + (lane >> 2) + rr * 8;
        size_t base = ((size_t)(b * S_) + row) * 1024 + h * 128;
        #pragma unroll
        for (int j = 0; j < 16; j++) {
            int c = j * 8 + (lane & 3) * 2;
            *(__half2*)&Out[base + c] =
                __floats2half2_rn(o[j][2 * rr] * inv, o[j][2 * rr + 1] * inv);
        }
    }
}

// ---------------- launch -----------------------------------------------------
extern "C" void kernel_launch(void* const* d_in, const int* in_sizes, int n_in,
                              void* d_out, int out_size) {
    const float* x        = (const float*)d_in[0];
    const int*   pos      = (const int*)d_in[1];
    const float* w_dq_w   = (const float*)d_in[2];
    const float* w_dq_b   = (const float*)d_in[3];
    const float* q_norm_w = (const float*)d_in[4];
    const float* w_uq_w   = (const float*)d_in[5];
    const float* w_uq_b   = (const float*)d_in[6];
    const float* w_dkv_w  = (const float*)d_in[7];
    const float* w_dkv_b  = (const float*)d_in[8];
    const float* kv_norm_w= (const float*)d_in[9];
    const float* w_ukuv_w = (const float*)d_in[10];
    const float* w_ukuv_b = (const float*)d_in[11];
    const float* w_o_w    = (const float*)d_in[12];
    const float* w_o_b    = (const float*)d_in[13];
    float* out = (float*)d_out;

    __half *xcat, *wdqkv, *cqcat, *wuqeff, *qe, *keff, *attnlat, *wfA, *wfB, *wfused;
    float *dqkv, *dqkv2, *bias_dqkv, *biaseff, *bopart, *boeff, *zb;
    cudaGetSymbolAddress((void**)&xcat,     g_xcat);
    cudaGetSymbolAddress((void**)&wdqkv,    g_wdqkv);
    cudaGetSymbolAddress((void**)&bias_dqkv,g_bias_dqkv);
    cudaGetSymbolAddress((void**)&dqkv,     g_dqkv);
    cudaGetSymbolAddress((void**)&dqkv2,    g_dqkv2);
    cudaGetSymbolAddress((void**)&cqcat,    g_cqcat);
    cudaGetSymbolAddress((void**)&wuqeff,   g_wuqeff);
    cudaGetSymbolAddress((void**)&biaseff,  g_biaseff);
    cudaGetSymbolAddress((void**)&qe,       g_qe);
    cudaGetSymbolAddress((void**)&keff,     g_keff);
    cudaGetSymbolAddress((void**)&attnlat,  g_attnlat);
    cudaGetSymbolAddress((void**)&wfA,      g_wfA);
    cudaGetSymbolAddress((void**)&wfB,      g_wfB);
    cudaGetSymbolAddress((void**)&wfused,   g_wfused);
    cudaGetSymbolAddress((void**)&bopart,   g_bopart);
    cudaGetSymbolAddress((void**)&boeff,    g_boeff);
    cudaGetSymbolAddress((void**)&zb,       g_zb);

    // ---- prep (independent) ----
    split_x<<<(T_ * 1024 + 255) / 256, 256>>>(x, xcat);
    prep_wdqkv<<<(1024 * 384 + 255) / 256, 256>>>(w_dq_w, w_dkv_w, wdqkv);
    prep_bias_dqkv<<<1, 384>>>(w_dq_b, w_dkv_b, bias_dqkv);
    cudaFuncSetAttribute(prep_wuqeff_gemm, cudaFuncAttributeMaxDynamicSharedMemorySize,
                         2 * 128 * 65 * (int)sizeof(float));
    prep_wuqeff_gemm<<<8, 256, 2 * 128 * 65 * sizeof(float)>>>(w_uq_w, w_ukuv_w, wuqeff);
    prep_wuqeff_pass<<<(128 * 512 + 255) / 256, 256>>>(w_uq_w, wuqeff);
    prep_biaseff<<<6, 256>>>(w_uq_b, w_ukuv_w, biaseff);
    prep_wfA<<<(8 * 128 * 256 + 255) / 256, 256>>>(w_ukuv_w, wfA);
    prep_wfB<<<(8 * 256 * 1024 + 255) / 256, 256>>>(w_o_w, wfB);
    prep_boeff1<<<dim3(4, 16), 256>>>(w_ukuv_b, w_o_w, bopart);
    prep_boeff2<<<4, 256>>>(w_o_b, bopart, boeff);

    // Wfused = W_uv @ W_o per head (split-fp16, batched over 8 heads)
    hgemm<1><<<dim3(8, 1, 8), 256>>>(wfA, wfB, zb, wfused, 128, 1024, 768, 768,
                                     (size_t)128 * 768, (size_t)768 * 1024,
                                     (size_t)128 * 1024, nullptr);

    // ---- main path ----
    // fused dq+dkv, split-K into two halves (each K=1536, lda=3072)
    hgemm<0><<<dim3(3, 32, 1), 256>>>(xcat, wdqkv, bias_dqkv, dqkv,
                                      T_, 384, 1536, 3072, 0, 0, 0, nullptr);
    hgemm<0><<<dim3(3, 32, 1), 256>>>(xcat + 1536, wdqkv + (size_t)1536 * 384, zb, dqkv2,
                                      T_, 384, 1536, 3072, 0, 0, 0, nullptr);
    // sum partials + norms + k-rope -> cqcat, keff
    postproc<<<T_, 128>>>(dqkv, dqkv2, pos, q_norm_w, kv_norm_w, cqcat, keff);
    // absorbed uq with fused rope epilogue -> qe directly (K=384)
    hgemm<2><<<dim3(12, 32, 1), 256>>>(cqcat, wuqeff, biaseff, qe,
                                       T_, 1536, 384, 384, 0, 0, 0, pos);

    // absorbed flash attention
    int fsmem = 128 * KP * (int)sizeof(__half);   // 51200
    cudaFuncSetAttribute(flash_mla, cudaFuncAttributeMaxDynamicSharedMemorySize, fsmem);
    flash_mla<<<dim3(S_ / 128, 16), 256, fsmem>>>(qe, keff, attnlat);

    // output projection: attn_lat @ Wfused + bo_eff
    hgemm<0><<<dim3(8, 32, 1), 256>>>(attnlat, wfused, boeff, out,
                                      T_, 1024, 1024, 1024, 0, 0, 0, nullptr);
}

// round 10
// speedup vs baseline: 14.5913x; 1.2515x over previous
#include <cuda_runtime.h>
#include <cuda_fp16.h>
#include <math.h>
#include <stdint.h>

#define B_   2
#define S_   2048
#define T_   4096      // B*S tokens
#define DIM_ 1024
#define SCALE_ 0.08838834764831845f   // 1/sqrt(128)

// ---------------- scratch (static device arrays) -----------------------------
__device__ __half g_xcat[T_ * 3072];       // [x_hi | x_lo | x_hi]
__device__ __half g_wdqkv[3072 * 384];     // stacked [Wdq|Wdkv] hi/hi/lo
__device__ float  g_bias_dqkv[384];
__device__ float  g_dqkv[2 * T_ * 384];    // split-K partials (contiguous)
__device__ __half g_cqcat[T_ * 384];       // [cq_hi | cq_lo | cq_hi]
__device__ __half g_wuqeff[384 * 1536];    // absorbed uq weights hi/hi/lo (scaled)
__device__ float  g_biaseff[1536];         // absorbed uq bias (scaled)
__device__ __half g_qe[16 * S_ * 192];     // q_eff [bh][s][192] fp16
__device__ __half g_keff[T_ * 192];        // [ckv_norm(128) | roped krope(64)]
__device__ __half g_attnlat[T_ * 1024];    // attn latent [t][h*128+c] fp16
__device__ __half g_wfA[8 * 128 * 768];    // Wfused GEMM A (split-K stacked)
__device__ __half g_wfB[8 * 768 * 1024];   // Wfused GEMM B
__device__ __half g_wfused[1024 * 1024];   // fused (W_uv @ W_o) fp16
__device__ float  g_bopart[16 * 1024];     // boeff partials
__device__ float  g_boeff[1024];           // b_o + sum_h b_uv W_o
__device__ float  g_zb[1536];              // zero bias (never written)

// ---------------- mma/ldmatrix/cp.async helpers ------------------------------
__device__ __forceinline__ uint32_t smem_u32(const void* p) {
    return (uint32_t)__cvta_generic_to_shared(p);
}
__device__ __forceinline__ void ldsm_x4(uint32_t* r, uint32_t addr) {
    asm volatile("ldmatrix.sync.aligned.m8n8.x4.shared.b16 {%0,%1,%2,%3},[%4];"
                 : "=r"(r[0]), "=r"(r[1]), "=r"(r[2]), "=r"(r[3]) : "r"(addr));
}
__device__ __forceinline__ void ldsm_x4_t(uint32_t* r, uint32_t addr) {
    asm volatile("ldmatrix.sync.aligned.m8n8.x4.trans.shared.b16 {%0,%1,%2,%3},[%4];"
                 : "=r"(r[0]), "=r"(r[1]), "=r"(r[2]), "=r"(r[3]) : "r"(addr));
}
__device__ __forceinline__ void mma16816(float* c, const uint32_t* a, const uint32_t* b) {
    asm volatile(
        "mma.sync.aligned.m16n8k16.row.col.f32.f16.f16.f32 "
        "{%0,%1,%2,%3},{%4,%5,%6,%7},{%8,%9},{%0,%1,%2,%3};"
        : "+f"(c[0]), "+f"(c[1]), "+f"(c[2]), "+f"(c[3])
        : "r"(a[0]), "r"(a[1]), "r"(a[2]), "r"(a[3]), "r"(b[0]), "r"(b[1]));
}
__device__ __forceinline__ uint32_t pack_h2(float lo, float hi) {
    __half2 h = __floats2half2_rn(lo, hi);
    return *(uint32_t*)&h;
}
__device__ __forceinline__ void cp16(void* smem_dst, const void* gsrc) {
    asm volatile("cp.async.cg.shared.global [%0],[%1],16;"
                 :: "r"(smem_u32(smem_dst)), "l"(gsrc));
}
#define CP_COMMIT() asm volatile("cp.async.commit_group;")
#define CP_WAIT(n)  asm volatile("cp.async.wait_group %0;" :: "n"(n))

__device__ __forceinline__ void split2(float v, __half& hi, __half& lo) {
    hi = __float2half(v);
    lo = __float2half(v - __half2float(hi));
}

// ================= MEGA PREP: all prep work in one launch =====================
// segments (block ranges):
#define NB_SPLITX 4096   // split_x: 4 elems/thread (float4)
#define NB_WDQKV  1536   // prep_wdqkv: 1 elem/thread
#define NB_BIASD  2      // bias dqkv
#define NB_WUQG   32     // wuqeff latent gemm: 8 heads x 4 row-tiles
#define NB_WUQP   256    // wuqeff passthrough
#define NB_BIASE  6      // biaseff
#define NB_WFA    1024   // wfA
#define NB_WFB    2048   // wfB: 4 elems/thread
#define NB_BOEFF  64     // boeff1 partials
#define OFF1 (NB_SPLITX)
#define OFF2 (OFF1 + NB_WDQKV)
#define OFF3 (OFF2 + NB_BIASD)
#define OFF4 (OFF3 + NB_WUQG)
#define OFF5 (OFF4 + NB_WUQP)
#define OFF6 (OFF5 + NB_BIASE)
#define OFF7 (OFF6 + NB_WFA)
#define OFF8 (OFF7 + NB_WFB)
#define NB_TOTAL (OFF8 + NB_BOEFF)

__global__ __launch_bounds__(256) void mega_prep(
    const float* __restrict__ x,
    const float* __restrict__ wdq, const float* __restrict__ wdkv,
    const float* __restrict__ bdq, const float* __restrict__ bdkv,
    const float* __restrict__ wuq, const float* __restrict__ buq,
    const float* __restrict__ wukuv, const float* __restrict__ bukuv,
    const float* __restrict__ wo,
    __half* __restrict__ xcat, __half* __restrict__ wdqkvc, float* __restrict__ biasd,
    __half* __restrict__ wuqeffc, float* __restrict__ biase,
    __half* __restrict__ wfA, __half* __restrict__ wfB, float* __restrict__ bopart) {
    __shared__ float Aq[64][33];    // [j][r] transposed, broadcast reads
    __shared__ float Bk[64][132];   // [j][c] transposed, LDS.128 reads

    int bid = blockIdx.x, tid = threadIdx.x;

    if (bid < OFF1) {
        // ---- split_x: x -> [x_hi | x_lo | x_hi] ----
        int i4 = bid * 256 + tid;
        int base = i4 * 4;
        int row = base >> 10, col = base & 1023;
        float4 v = *(const float4*)(x + base);
        __half h0, l0, h1, l1, h2, l2, h3, l3;
        split2(v.x, h0, l0); split2(v.y, h1, l1);
        split2(v.z, h2, l2); split2(v.w, h3, l3);
        __half* r = xcat + (size_t)row * 3072 + col;
        *(__half2*)(r + 0) = __halves2half2(h0, h1);
        *(__half2*)(r + 2) = __halves2half2(h2, h3);
        *(__half2*)(r + 1024) = __halves2half2(l0, l1);
        *(__half2*)(r + 1026) = __halves2half2(l2, l3);
        *(__half2*)(r + 2048) = __halves2half2(h0, h1);
        *(__half2*)(r + 2050) = __halves2half2(h2, h3);
    } else if (bid < OFF2) {
        // ---- stacked [Wdq|Wdkv] ----
        int i = (bid - OFF1) * 256 + tid;
        if (i < 1024 * 384) {
            int k = i / 384, j = i - k * 384;
            float v = (j < 128) ? wdq[k * 128 + j]
                                : (j < 320 ? wdkv[k * 192 + (j - 128)] : 0.f);
            __half hi, lo; split2(v, hi, lo);
            wdqkvc[(size_t)k * 384 + j] = hi;
            wdqkvc[(size_t)(1024 + k) * 384 + j] = hi;
            wdqkvc[(size_t)(2048 + k) * 384 + j] = lo;
        }
    } else if (bid < OFF3) {
        // ---- dqkv bias ----
        int j = (bid - OFF2) * 256 + tid;
        if (j < 384)
            biasd[j] = (j < 128) ? bdq[j] : (j < 320 ? bdkv[j - 128] : 0.f);
    } else if (bid < OFF4) {
        // ---- wuqeff latent block: per-head GEMM 32rows x 128cols x K=64 ----
        int bid2 = bid - OFF3;
        int h = bid2 >> 2, r0 = (bid2 & 3) * 32;
        // load A (32x64 of wuq) transposed -> Aq[j][r]
        #pragma unroll
        for (int it = 0; it < 8; it++) {
            int e = it * 256 + tid;          // 0..2047
            int r = e >> 6, j = e & 63;
            Aq[j][r] = wuq[(size_t)(r0 + r) * 1024 + h * 96 + j];
        }
        // load B (128x64 of wukuv rows=c) transposed -> Bk[j][c]
        #pragma unroll
        for (int it = 0; it < 32; it++) {
            int e = it * 256 + tid;          // 0..8191
            int c = e >> 6, j = e & 63;
            Bk[j][c] = wukuv[(size_t)c * 2560 + h * 64 + j];
        }
        __syncthreads();
        int ty = tid >> 5, tx = tid & 31;    // 8 row groups x 32 col groups
        float acc[4][4];
        #pragma unroll
        for (int i = 0; i < 4; i++)
            #pragma unroll
            for (int k = 0; k < 4; k++) acc[i][k] = 0.f;
        #pragma unroll 8
        for (int j = 0; j < 64; j++) {
            float a[4];
            #pragma unroll
            for (int i = 0; i < 4; i++) a[i] = Aq[j][ty * 4 + i];
            float4 b4 = *(float4*)&Bk[j][tx * 4];
            float bb[4] = {b4.x, b4.y, b4.z, b4.w};
            #pragma unroll
            for (int i = 0; i < 4; i++)
                #pragma unroll
                for (int k = 0; k < 4; k++) acc[i][k] += a[i] * bb[k];
        }
        #pragma unroll
        for (int i = 0; i < 4; i++) {
            #pragma unroll
            for (int k = 0; k < 4; k++) {
                float v = acc[i][k] * SCALE_;
                __half hi, lo; split2(v, hi, lo);
                int r = r0 + ty * 4 + i;
                int col = h * 192 + tx * 4 + k;
                wuqeffc[(size_t)r * 1536 + col] = hi;
                wuqeffc[(size_t)(128 + r) * 1536 + col] = hi;
                wuqeffc[(size_t)(256 + r) * 1536 + col] = lo;
            }
        }
    } else if (bid < OFF5) {
        // ---- wuqeff passthrough cols ----
        int i = (bid - OFF4) * 256 + tid;
        if (i < 128 * 512) {
            int r = i >> 9, rem = i & 511;
            int h = rem >> 6, cc = rem & 63;
            float v = (cc < 32) ? wuq[(size_t)r * 1024 + h * 96 + 64 + cc]
                                : wuq[(size_t)r * 1024 + 768 + h * 32 + (cc - 32)];
            v *= SCALE_;
            __half hi, lo; split2(v, hi, lo);
            int col = h * 192 + 128 + cc;
            wuqeffc[(size_t)r * 1536 + col] = hi;
            wuqeffc[(size_t)(128 + r) * 1536 + col] = hi;
            wuqeffc[(size_t)(256 + r) * 1536 + col] = lo;
        }
    } else if (bid < OFF6) {
        // ---- biaseff ----
        int col = (bid - OFF5) * 256 + tid;
        if (col < 1536) {
            int h = col / 192, c = col - h * 192;
            float v;
            if (c < 128) {
                float s = 0.f;
                const float* bq = buq + h * 96;
                const float* wk = wukuv + (size_t)c * 2560 + h * 64;
                #pragma unroll 8
                for (int j = 0; j < 64; j++) s += bq[j] * wk[j];
                v = s;
            } else if (c < 160) {
                v = buq[h * 96 + 64 + (c - 128)];
            } else {
                v = buq[768 + h * 32 + (c - 160)];
            }
            biase[col] = v * SCALE_;
        }
    } else if (bid < OFF7) {
        // ---- wfA ----
        int i = (bid - OFF6) * 256 + tid;
        if (i < 8 * 128 * 256) {
            int h = i >> 15, rem = i & 32767;
            int c = rem >> 8, v = rem & 255;
            float val = wukuv[(size_t)c * 2560 + 512 + h * 256 + v];
            __half hi, lo; split2(val, hi, lo);
            __half* base = wfA + ((size_t)h * 128 + c) * 768;
            base[v] = hi;
            base[256 + v] = lo;
            base[512 + v] = hi;
        }
    } else if (bid < OFF8) {
        // ---- wfB (4 elems/thread, float4) ----
        int i4 = (bid - OFF7) * 256 + tid;
        int elem = i4 * 4;
        int h = elem >> 18, rem = elem & 262143;
        int v = rem >> 10, o = rem & 1023;
        float4 val = *(const float4*)(wo + ((size_t)h * 256 + v) * 1024 + o);
        __half h0, l0, h1, l1, h2, l2, h3, l3;
        split2(val.x, h0, l0); split2(val.y, h1, l1);
        split2(val.z, h2, l2); split2(val.w, h3, l3);
        __half* base = wfB + (size_t)h * 768 * 1024;
        __half* p0 = base + (size_t)v * 1024 + o;
        __half* p1 = base + (size_t)(256 + v) * 1024 + o;
        __half* p2 = base + (size_t)(512 + v) * 1024 + o;
        *(__half2*)(p0 + 0) = __halves2half2(h0, h1);
        *(__half2*)(p0 + 2) = __halves2half2(h2, h3);
        *(__half2*)(p1 + 0) = __halves2half2(h0, h1);
        *(__half2*)(p1 + 2) = __halves2half2(h2, h3);
        *(__half2*)(p2 + 0) = __halves2half2(l0, l1);
        *(__half2*)(p2 + 2) = __halves2half2(l2, l3);
    } else {
        // ---- boeff partials ----
        int bid2 = bid - OFF8;
        int z = bid2 >> 2;
        int o = (bid2 & 3) * 256 + tid;
        float s = 0.f;
        #pragma unroll 8
        for (int r = z * 128; r < (z + 1) * 128; r++)
            s += bukuv[512 + r] * wo[(size_t)r * 1024 + o];
        bopart[(size_t)z * 1024 + o] = s;
    }
}

__global__ void prep_boeff2(const float* __restrict__ bo, const float* __restrict__ part,
                            float* __restrict__ be) {
    int o = blockIdx.x * 256 + threadIdx.x;
    float s = bo[o];
    #pragma unroll
    for (int z = 0; z < 16; z++) s += part[(size_t)z * 1024 + o];
    be[o] = s;
}

// ---------------- fp16 tensor-core GEMM (double-buffered, batched-z) ---------
// MODE 0: float out (bias only for z==0). MODE 1: half out. MODE 2: qe layout + rope.
template <int MODE>
__global__ __launch_bounds__(256, 2) void hgemm(
    const __half* __restrict__ A, const __half* __restrict__ Bm,
    const float* __restrict__ bias, void* __restrict__ Cv, int M, int N, int K,
    int lda, size_t zA, size_t zB, size_t zC, const int* __restrict__ pos) {
    __shared__ __half As[2][128][40];
    __shared__ __half Bs[2][32][136];

    A += blockIdx.z * zA;
    Bm += blockIdx.z * zB;

    int tid = threadIdx.x, lane = tid & 31, w = tid >> 5;
    int wr = w >> 2, wc = w & 3;
    int row0 = blockIdx.y * 128, col0 = blockIdx.x * 128;

    float acc[16][4];
    #pragma unroll
    for (int i = 0; i < 16; i++)
        #pragma unroll
        for (int j = 0; j < 4; j++) acc[i][j] = 0.f;

    int nk = K >> 5;
    {
        const __half* Ab = A + (size_t)row0 * lda;
        #pragma unroll
        for (int it = 0; it < 2; it++) {
            int e = it * 256 + tid;
            int r = e >> 2, c = (e & 3) * 8;
            cp16(&As[0][r][c], Ab + (size_t)r * lda + c);
        }
        #pragma unroll
        for (int it = 0; it < 2; it++) {
            int e = it * 256 + tid;
            int r = e >> 4, c = (e & 15) * 8;
            cp16(&Bs[0][r][c], Bm + (size_t)r * N + col0 + c);
        }
    }
    CP_COMMIT();

    for (int kt = 0; kt < nk; kt++) {
        int cur = kt & 1;
        if (kt + 1 < nk) {
            int k0 = (kt + 1) << 5;
            const __half* Ab = A + (size_t)row0 * lda + k0;
            #pragma unroll
            for (int it = 0; it < 2; it++) {
                int e = it * 256 + tid;
                int r = e >> 2, c = (e & 3) * 8;
                cp16(&As[cur ^ 1][r][c], Ab + (size_t)r * lda + c);
            }
            const __half* Bb = Bm + (size_t)k0 * N + col0;
            #pragma unroll
            for (int it = 0; it < 2; it++) {
                int e = it * 256 + tid;
                int r = e >> 4, c = (e & 15) * 8;
                cp16(&Bs[cur ^ 1][r][c], Bb + (size_t)r * N + c);
            }
        }
        CP_COMMIT();
        CP_WAIT(1);
        __syncthreads();

        #pragma unroll
        for (int kk = 0; kk < 2; kk++) {
            uint32_t af[4][4], bf[2][4];
            #pragma unroll
            for (int mt = 0; mt < 4; mt++) {
                int r = wr * 64 + mt * 16 + (lane & 15);
                int c = kk * 16 + ((lane >> 4) << 3);
                ldsm_x4(af[mt], smem_u32(&As[cur][r][c]));
            }
            #pragma unroll
            for (int nt2 = 0; nt2 < 2; nt2++) {
                int kr = kk * 16 + (lane & 7) + (lane & 8);
                int nc = wc * 32 + nt2 * 16 + ((lane >> 4) << 3);
                ldsm_x4_t(bf[nt2], smem_u32(&Bs[cur][kr][nc]));
            }
            #pragma unroll
            for (int mt = 0; mt < 4; mt++)
                #pragma unroll
                for (int nt = 0; nt < 4; nt++)
                    mma16816(acc[mt * 4 + nt], af[mt], bf[nt >> 1] + (nt & 1) * 2);
        }
        __syncthreads();
    }

    float bz = (MODE == 0 && blockIdx.z > 0) ? 0.f : 1.f;
    #pragma unroll
    for (int mt = 0; mt < 4; mt++) {
        #pragma unroll
        for (int nt = 0; nt < 4; nt++) {
            int row = row0 + wr * 64 + mt * 16 + (lane >> 2);
            int col = col0 + wc * 32 + nt * 8 + (lane & 3) * 2;
            float b0 = bias[col] * bz, b1 = bias[col + 1] * bz;
            float v0 = acc[mt * 4 + nt][0] + b0;
            float v1 = acc[mt * 4 + nt][1] + b1;
            float v2 = acc[mt * 4 + nt][2] + b0;
            float v3 = acc[mt * 4 + nt][3] + b1;
            if (MODE == 0) {
                float* C = (float*)Cv + blockIdx.z * zC;
                *(float2*)(C + (size_t)row * N + col) = make_float2(v0, v1);
                *(float2*)(C + (size_t)(row + 8) * N + col) = make_float2(v2, v3);
            } else if (MODE == 1) {
                __half* C = (__half*)Cv + blockIdx.z * zC;
                *(__half2*)(C + (size_t)row * N + col) = __floats2half2_rn(v0, v1);
                *(__half2*)(C + (size_t)(row + 8) * N + col) = __floats2half2_rn(v2, v3);
            } else {
                // qe layout: [bh][s][192], rope on cols c>=160 (pairs in-thread)
                __half* C = (__half*)Cv;
                int h = col / 192, c = col - h * 192;
                if (c >= 160) {
                    int i2 = (c - 160) >> 1;
                    float freq = powf(10000.f, -(float)(2 * i2) / 32.f);
                    float p0f = (float)pos[row], p1f = (float)pos[row + 8];
                    float a0 = p0f * freq, a1 = p1f * freq;
                    float c0 = cosf(a0), s0 = sinf(a0);
                    float c1 = cosf(a1), s1 = sinf(a1);
                    float t0 = v0 * c0 - v1 * s0, t1 = v0 * s0 + v1 * c0;
                    v0 = t0; v1 = t1;
                    t0 = v2 * c1 - v3 * s1; t1 = v2 * s1 + v3 * c1;
                    v2 = t0; v3 = t1;
                }
                int b = row >> 11, s = row & 2047;
                *(__half2*)(C + (((size_t)(b * 8 + h)) * S_ + s) * 192 + c) =
                    __floats2half2_rn(v0, v1);
                int row2 = row + 8;
                b = row2 >> 11; s = row2 & 2047;
                *(__half2*)(C + (((size_t)(b * 8 + h)) * S_ + s) * 192 + c) =
                    __floats2half2_rn(v2, v3);
            }
        }
    }
}

// ---------------- fused post-dqkv: sum split-K + 2x rmsnorm + k-rope ---------
__global__ void postproc(const float* __restrict__ dqkvA, const float* __restrict__ dqkvB,
                         const int* __restrict__ pos,
                         const float* __restrict__ qnw, const float* __restrict__ kvnw,
                         __half* __restrict__ cqcat, __half* __restrict__ keff) {
    __shared__ float r1[128], r2[128];
    int t = blockIdx.x, d = threadIdx.x;
    const float* rowA = dqkvA + (size_t)t * 384;
    const float* rowB = dqkvB + (size_t)t * 384;
    float qv = rowA[d] + rowB[d];
    float kvv = rowA[128 + d] + rowB[128 + d];
    r1[d] = qv * qv;
    r2[d] = kvv * kvv;
    __syncthreads();
    #pragma unroll
    for (int s = 64; s > 0; s >>= 1) {
        if (d < s) { r1[d] += r1[d + s]; r2[d] += r2[d + s]; }
        __syncthreads();
    }
    float invq = rsqrtf(r1[0] * (1.f / 128.f) + 1e-8f);
    float invk = rsqrtf(r2[0] * (1.f / 128.f) + 1e-8f);
    float cq = qnw[d] * qv * invq;
    __half hi, lo; split2(cq, hi, lo);
    __half* cr = cqcat + (size_t)t * 384;
    cr[d] = hi;
    cr[128 + d] = lo;
    cr[256 + d] = hi;
    keff[(size_t)t * 192 + d] = __float2half(kvnw[d] * kvv * invk);
    if (d < 32) {
        float p = (float)pos[t];
        float freq = powf(10000.f, -(float)(2 * d) / 64.f);
        float ang = p * freq;
        float c = cosf(ang), s = sinf(ang);
        float xe = rowA[256 + 2 * d] + rowB[256 + 2 * d];
        float xo = rowA[256 + 2 * d + 1] + rowB[256 + 2 * d + 1];
        keff[(size_t)t * 192 + 128 + 2 * d]     = __float2half(xe * c - xo * s);
        keff[(size_t)t * 192 + 128 + 2 * d + 1] = __float2half(xe * s + xo * c);
    }
}

// ---------------- absorbed flash attention -----------------------------------
#define KP 200
__global__ __launch_bounds__(256, 1) void flash_mla(
    const __half* __restrict__ Qe, const __half* __restrict__ Ke,
    __half* __restrict__ Out) {
    extern __shared__ __half sm[];   // 2 stages x 64 x KP (50 KB)

    int tid = threadIdx.x, lane = tid & 31, w = tid >> 5;
    int bh = blockIdx.y;
    int b = bh >> 3, h = bh & 7;
    int q0 = blockIdx.x * 128;

    {
        const __half* qbase = Qe + ((size_t)bh * S_ + q0) * 192;
        #pragma unroll
        for (int it = 0; it < 12; it++) {
            int e = it * 256 + tid;
            int r = e / 24, c = (e % 24) * 8;
            cp16(&sm[r * KP + c], qbase + (size_t)r * 192 + c);
        }
    }
    CP_COMMIT();
    CP_WAIT(0);
    __syncthreads();

    uint32_t qf[12][4];
    #pragma unroll
    for (int ks = 0; ks < 12; ks++) {
        int r = w * 16 + (lane & 15);
        int c = ks * 16 + ((lane >> 4) << 3);
        ldsm_x4(qf[ks], smem_u32(&sm[r * KP + c]));
    }
    __syncthreads();

    const __half* kbase = Ke + (size_t)b * S_ * 192;

    #pragma unroll
    for (int it = 0; it < 6; it++) {
        int e = it * 256 + tid;
        int r = e / 24, c = (e % 24) * 8;
        cp16(&sm[r * KP + c], kbase + (size_t)r * 192 + c);
    }
    CP_COMMIT();

    float m[2] = {-1e30f, -1e30f}, l[2] = {0.f, 0.f};
    float o[16][4];
    #pragma unroll
    for (int i = 0; i < 16; i++)
        #pragma unroll
        for (int j = 0; j < 4; j++) o[i][j] = 0.f;

    for (int kb = 0; kb < S_ / 64; kb++) {
        int cur = kb & 1;
        if (kb + 1 < S_ / 64) {
            const __half* kb2 = kbase + (size_t)(kb + 1) * 64 * 192;
            __half* Kd = sm + (cur ^ 1) * 64 * KP;
            #pragma unroll
            for (int it = 0; it < 6; it++) {
                int e = it * 256 + tid;
                int r = e / 24, c = (e % 24) * 8;
                cp16(&Kd[r * KP + c], kb2 + (size_t)r * 192 + c);
            }
        }
        CP_COMMIT();
        CP_WAIT(1);
        __syncthreads();

        const __half* Ks = sm + cur * 64 * KP;

        float s[8][4];
        #pragma unroll
        for (int i = 0; i < 8; i++)
            #pragma unroll
            for (int j = 0; j < 4; j++) s[i][j] = 0.f;
        #pragma unroll
        for (int ks = 0; ks < 12; ks++) {
            #pragma unroll
            for (int nt2 = 0; nt2 < 4; nt2++) {
                uint32_t bfr[4];
                int n = nt2 * 16 + ((lane >> 4) << 3) + (lane & 7);
                int k = ks * 16 + (lane & 8);
                ldsm_x4(bfr, smem_u32(&Ks[n * KP + k]));
                mma16816(s[2 * nt2],     qf[ks], bfr + 0);
                mma16816(s[2 * nt2 + 1], qf[ks], bfr + 2);
            }
        }

        #pragma unroll
        for (int rr = 0; rr < 2; rr++) {
            float mx = -1e30f;
            #pragma unroll
            for (int j = 0; j < 8; j++)
                mx = fmaxf(mx, fmaxf(s[j][2 * rr], s[j][2 * rr + 1]));
            mx = fmaxf(mx, __shfl_xor_sync(0xffffffffu, mx, 1));
            mx = fmaxf(mx, __shfl_xor_sync(0xffffffffu, mx, 2));
            float m_new = fmaxf(m[rr], mx);
            float alpha = __expf(m[rr] - m_new);
            float tsum = 0.f;
            #pragma unroll
            for (int j = 0; j < 8; j++) {
                float p0 = __expf(s[j][2 * rr] - m_new);
                float p1 = __expf(s[j][2 * rr + 1] - m_new);
                s[j][2 * rr] = p0;
                s[j][2 * rr + 1] = p1;
                tsum += p0 + p1;
            }
            tsum += __shfl_xor_sync(0xffffffffu, tsum, 1);
            tsum += __shfl_xor_sync(0xffffffffu, tsum, 2);
            l[rr] = l[rr] * alpha + tsum;
            m[rr] = m_new;
            #pragma unroll
            for (int j = 0; j < 16; j++) {
                o[j][2 * rr] *= alpha;
                o[j][2 * rr + 1] *= alpha;
            }
        }

        uint32_t pf[4][4];
        #pragma unroll
        for (int kk = 0; kk < 4; kk++) {
            pf[kk][0] = pack_h2(s[2 * kk][0],     s[2 * kk][1]);
            pf[kk][1] = pack_h2(s[2 * kk][2],     s[2 * kk][3]);
            pf[kk][2] = pack_h2(s[2 * kk + 1][0], s[2 * kk + 1][1]);
            pf[kk][3] = pack_h2(s[2 * kk + 1][2], s[2 * kk + 1][3]);
        }

        #pragma unroll
        for (int kk = 0; kk < 4; kk++) {
            #pragma unroll
            for (int nt2 = 0; nt2 < 8; nt2++) {
                uint32_t bfr[4];
                int k = kk * 16 + (lane & 7) + (lane & 8);
                int n = nt2 * 16 + ((lane >> 4) << 3);
                ldsm_x4_t(bfr, smem_u32(&Ks[k * KP + n]));
                mma16816(o[2 * nt2],     pf[kk], bfr + 0);
                mma16816(o[2 * nt2 + 1], pf[kk], bfr + 2);
            }
        }
        __syncthreads();
    }

    #pragma unroll
    for (int rr = 0; rr < 2; rr++) {
        float inv = 1.f / l[rr];
        int row = q0 + w * 16 + (lane >> 2) + rr * 8;
        size_t base = ((size_t)(b * S_) + row) * 1024 + h * 128;
        #pragma unroll
        for (int j = 0; j < 16; j++) {
            int c = j * 8 + (lane & 3) * 2;
            *(__half2*)&Out[base + c] =
                __floats2half2_rn(o[j][2 * rr] * inv, o[j][2 * rr + 1] * inv);
        }
    }
}

// ---------------- launch -----------------------------------------------------
extern "C" void kernel_launch(void* const* d_in, const int* in_sizes, int n_in,
                              void* d_out, int out_size) {
    const float* x        = (const float*)d_in[0];
    const int*   pos      = (const int*)d_in[1];
    const float* w_dq_w   = (const float*)d_in[2];
    const float* w_dq_b   = (const float*)d_in[3];
    const float* q_norm_w = (const float*)d_in[4];
    const float* w_uq_w   = (const float*)d_in[5];
    const float* w_uq_b   = (const float*)d_in[6];
    const float* w_dkv_w  = (const float*)d_in[7];
    const float* w_dkv_b  = (const float*)d_in[8];
    const float* kv_norm_w= (const float*)d_in[9];
    const float* w_ukuv_w = (const float*)d_in[10];
    const float* w_ukuv_b = (const float*)d_in[11];
    const float* w_o_w    = (const float*)d_in[12];
    const float* w_o_b    = (const float*)d_in[13];
    float* out = (float*)d_out;

    __half *xcat, *wdqkv, *cqcat, *wuqeff, *qe, *keff, *attnlat, *wfA, *wfB, *wfused;
    float *dqkv, *bias_dqkv, *biaseff, *bopart, *boeff, *zb;
    cudaGetSymbolAddress((void**)&xcat,     g_xcat);
    cudaGetSymbolAddress((void**)&wdqkv,    g_wdqkv);
    cudaGetSymbolAddress((void**)&bias_dqkv,g_bias_dqkv);
    cudaGetSymbolAddress((void**)&dqkv,     g_dqkv);
    cudaGetSymbolAddress((void**)&cqcat,    g_cqcat);
    cudaGetSymbolAddress((void**)&wuqeff,   g_wuqeff);
    cudaGetSymbolAddress((void**)&biaseff,  g_biaseff);
    cudaGetSymbolAddress((void**)&qe,       g_qe);
    cudaGetSymbolAddress((void**)&keff,     g_keff);
    cudaGetSymbolAddress((void**)&attnlat,  g_attnlat);
    cudaGetSymbolAddress((void**)&wfA,      g_wfA);
    cudaGetSymbolAddress((void**)&wfB,      g_wfB);
    cudaGetSymbolAddress((void**)&wfused,   g_wfused);
    cudaGetSymbolAddress((void**)&bopart,   g_bopart);
    cudaGetSymbolAddress((void**)&boeff,    g_boeff);
    cudaGetSymbolAddress((void**)&zb,       g_zb);

    // ---- all prep in one launch ----
    mega_prep<<<NB_TOTAL, 256>>>(x, w_dq_w, w_dkv_w, w_dq_b, w_dkv_b, w_uq_w, w_uq_b,
                                 w_ukuv_w, w_ukuv_b, w_o_w,
                                 xcat, wdqkv, bias_dqkv, wuqeff, biaseff, wfA, wfB, bopart);
    prep_boeff2<<<4, 256>>>(w_o_b, bopart, boeff);

    // Wfused = W_uv @ W_o per head (split-fp16, batched over 8 heads)
    hgemm<1><<<dim3(8, 1, 8), 256>>>(wfA, wfB, zb, wfused, 128, 1024, 768, 768,
                                     (size_t)128 * 768, (size_t)768 * 1024,
                                     (size_t)128 * 1024, nullptr);

    // ---- main path ----
    // fused dq+dkv, split-K batched over z (each K=1536, lda=3072)
    hgemm<0><<<dim3(3, 32, 2), 256>>>(xcat, wdqkv, bias_dqkv, dqkv,
                                      T_, 384, 1536, 3072,
                                      (size_t)1536, (size_t)1536 * 384,
                                      (size_t)T_ * 384, nullptr);
    // sum partials + norms + k-rope -> cqcat, keff
    postproc<<<T_, 128>>>(dqkv, dqkv + (size_t)T_ * 384, pos, q_norm_w, kv_norm_w,
                          cqcat, keff);
    // absorbed uq with fused rope epilogue -> qe directly (K=384)
    hgemm<2><<<dim3(12, 32, 1), 256>>>(cqcat, wuqeff, biaseff, qe,
                                       T_, 1536, 384, 384, 0, 0, 0, pos);

    // absorbed flash attention
    int fsmem = 128 * KP * (int)sizeof(__half);   // 51200
    cudaFuncSetAttribute(flash_mla, cudaFuncAttributeMaxDynamicSharedMemorySize, fsmem);
    flash_mla<<<dim3(S_ / 128, 16), 256, fsmem>>>(qe, keff, attnlat);

    // output projection: attn_lat @ Wfused + bo_eff
    hgemm<0><<<dim3(8, 32, 1), 256>>>(attnlat, wfused, boeff, out,
                                      T_, 1024, 1024, 1024, 0, 0, 0, nullptr);
}

// round 12
// speedup vs baseline: 14.9207x; 1.0226x over previous
#include <cuda_runtime.h>
#include <cuda_fp16.h>
#include <math.h>
#include <stdint.h>

#define B_   2
#define S_   2048
#define T_   4096      // B*S tokens
#define DIM_ 1024
#define SCALE_ 0.08838834764831845f   // 1/sqrt(128)

// ---------------- scratch (static device arrays) -----------------------------
__device__ __half g_xcat[T_ * 3072];       // [x_hi | x_lo | x_hi]
__device__ __half g_wdqkv[3072 * 384];     // stacked [Wdq|Wdkv] hi/hi/lo
__device__ float  g_bias_dqkv[384];
__device__ float  g_dqkv[2 * T_ * 384];    // split-K partials (contiguous)
__device__ __half g_cqcat[T_ * 384];       // [cq_hi | cq_lo | cq_hi]
__device__ __half g_wuqeff[384 * 1536];    // absorbed uq weights hi/hi/lo (scaled)
__device__ float  g_biaseff[1536];         // absorbed uq bias (scaled)
__device__ __half g_qe[16 * S_ * 192];     // q_eff [bh][s][192] fp16
__device__ __half g_keff[T_ * 192];        // [ckv_norm(128) | roped krope(64)]
__device__ __half g_attnlat[T_ * 1024];    // attn latent [t][h*128+c] fp16
__device__ __half g_wfA[8 * 128 * 768];    // Wfused GEMM A (split-K stacked)
__device__ __half g_wfB[8 * 768 * 1024];   // Wfused GEMM B
__device__ __half g_wfused[1024 * 1024];   // fused (W_uv @ W_o) fp16
__device__ float  g_bopart[16 * 1024];     // boeff partials
__device__ float  g_boeff[1024];           // b_o + sum_h b_uv W_o
__device__ float  g_zb[1536];              // zero bias (never written)

// ---------------- mma/ldmatrix/cp.async helpers ------------------------------
__device__ __forceinline__ uint32_t smem_u32(const void* p) {
    return (uint32_t)__cvta_generic_to_shared(p);
}
__device__ __forceinline__ void ldsm_x4(uint32_t* r, uint32_t addr) {
    asm volatile("ldmatrix.sync.aligned.m8n8.x4.shared.b16 {%0,%1,%2,%3},[%4];"
                 : "=r"(r[0]), "=r"(r[1]), "=r"(r[2]), "=r"(r[3]) : "r"(addr));
}
__device__ __forceinline__ void ldsm_x4_t(uint32_t* r, uint32_t addr) {
    asm volatile("ldmatrix.sync.aligned.m8n8.x4.trans.shared.b16 {%0,%1,%2,%3},[%4];"
                 : "=r"(r[0]), "=r"(r[1]), "=r"(r[2]), "=r"(r[3]) : "r"(addr));
}
__device__ __forceinline__ void mma16816(float* c, const uint32_t* a, const uint32_t* b) {
    asm volatile(
        "mma.sync.aligned.m16n8k16.row.col.f32.f16.f16.f32 "
        "{%0,%1,%2,%3},{%4,%5,%6,%7},{%8,%9},{%0,%1,%2,%3};"
        : "+f"(c[0]), "+f"(c[1]), "+f"(c[2]), "+f"(c[3])
        : "r"(a[0]), "r"(a[1]), "r"(a[2]), "r"(a[3]), "r"(b[0]), "r"(b[1]));
}
__device__ __forceinline__ uint32_t pack_h2(float lo, float hi) {
    __half2 h = __floats2half2_rn(lo, hi);
    return *(uint32_t*)&h;
}
__device__ __forceinline__ void cp16(void* smem_dst, const void* gsrc) {
    asm volatile("cp.async.cg.shared.global [%0],[%1],16;"
                 :: "r"(smem_u32(smem_dst)), "l"(gsrc));
}
#define CP_COMMIT() asm volatile("cp.async.commit_group;")
#define CP_WAIT(n)  asm volatile("cp.async.wait_group %0;" :: "n"(n))

__device__ __forceinline__ void split2(float v, __half& hi, __half& lo) {
    hi = __float2half(v);
    lo = __float2half(v - __half2float(hi));
}

// ================= PREP A (token path): split_x + wdqkv + bias ================
#define NB_SPLITX 4096
#define NB_WDQKV  1536
#define NB_BIASD  2
#define PA_OFF1 (NB_SPLITX)
#define PA_OFF2 (PA_OFF1 + NB_WDQKV)
#define PA_TOTAL (PA_OFF2 + NB_BIASD)

__global__ __launch_bounds__(256) void prep_a(
    const float* __restrict__ x,
    const float* __restrict__ wdq, const float* __restrict__ wdkv,
    const float* __restrict__ bdq, const float* __restrict__ bdkv,
    __half* __restrict__ xcat, __half* __restrict__ wdqkvc, float* __restrict__ biasd) {
    int bid = blockIdx.x, tid = threadIdx.x;
    if (bid < PA_OFF1) {
        int i4 = bid * 256 + tid;
        int base = i4 * 4;
        int row = base >> 10, col = base & 1023;
        float4 v = *(const float4*)(x + base);
        __half h0, l0, h1, l1, h2, l2, h3, l3;
        split2(v.x, h0, l0); split2(v.y, h1, l1);
        split2(v.z, h2, l2); split2(v.w, h3, l3);
        __half* r = xcat + (size_t)row * 3072 + col;
        *(__half2*)(r + 0) = __halves2half2(h0, h1);
        *(__half2*)(r + 2) = __halves2half2(h2, h3);
        *(__half2*)(r + 1024) = __halves2half2(l0, l1);
        *(__half2*)(r + 1026) = __halves2half2(l2, l3);
        *(__half2*)(r + 2048) = __halves2half2(h0, h1);
        *(__half2*)(r + 2050) = __halves2half2(h2, h3);
    } else if (bid < PA_OFF2) {
        int i = (bid - PA_OFF1) * 256 + tid;
        if (i < 1024 * 384) {
            int k = i / 384, j = i - k * 384;
            float v = (j < 128) ? wdq[k * 128 + j]
                                : (j < 320 ? wdkv[k * 192 + (j - 128)] : 0.f);
            __half hi, lo; split2(v, hi, lo);
            wdqkvc[(size_t)k * 384 + j] = hi;
            wdqkvc[(size_t)(1024 + k) * 384 + j] = hi;
            wdqkvc[(size_t)(2048 + k) * 384 + j] = lo;
        }
    } else {
        int j = (bid - PA_OFF2) * 256 + tid;
        if (j < 384)
            biasd[j] = (j < 128) ? bdq[j] : (j < 320 ? bdkv[j - 128] : 0.f);
    }
}

// ================= PREP B (weight path): wuqeff/biaseff/wfA/wfB/boeff1 =======
#define NB_WUQG   32
#define NB_WUQP   256
#define NB_BIASE  6
#define NB_WFA    1024
#define NB_WFB    2048
#define NB_BOEFF  64
#define PB_OFF1 (NB_WUQG)
#define PB_OFF2 (PB_OFF1 + NB_WUQP)
#define PB_OFF3 (PB_OFF2 + NB_BIASE)
#define PB_OFF4 (PB_OFF3 + NB_WFA)
#define PB_OFF5 (PB_OFF4 + NB_WFB)
#define PB_TOTAL (PB_OFF5 + NB_BOEFF)

__global__ __launch_bounds__(256) void prep_b(
    const float* __restrict__ wuq, const float* __restrict__ buq,
    const float* __restrict__ wukuv, const float* __restrict__ bukuv,
    const float* __restrict__ wo,
    __half* __restrict__ wuqeffc, float* __restrict__ biase,
    __half* __restrict__ wfA, __half* __restrict__ wfB, float* __restrict__ bopart) {
    __shared__ float Aq[64][33];
    __shared__ float Bk[64][132];
    int bid = blockIdx.x, tid = threadIdx.x;

    if (bid < PB_OFF1) {
        // wuqeff latent gemm: 8 heads x 4 row-tiles of 32, K=64
        int h = bid >> 2, r0 = (bid & 3) * 32;
        #pragma unroll
        for (int it = 0; it < 8; it++) {
            int e = it * 256 + tid;
            int r = e >> 6, j = e & 63;
            Aq[j][r] = wuq[(size_t)(r0 + r) * 1024 + h * 96 + j];
        }
        #pragma unroll
        for (int it = 0; it < 32; it++) {
            int e = it * 256 + tid;
            int c = e >> 6, j = e & 63;
            Bk[j][c] = wukuv[(size_t)c * 2560 + h * 64 + j];
        }
        __syncthreads();
        int ty = tid >> 5, tx = tid & 31;
        float acc[4][4];
        #pragma unroll
        for (int i = 0; i < 4; i++)
            #pragma unroll
            for (int k = 0; k < 4; k++) acc[i][k] = 0.f;
        #pragma unroll 8
        for (int j = 0; j < 64; j++) {
            float a[4];
            #pragma unroll
            for (int i = 0; i < 4; i++) a[i] = Aq[j][ty * 4 + i];
            float4 b4 = *(float4*)&Bk[j][tx * 4];
            float bb[4] = {b4.x, b4.y, b4.z, b4.w};
            #pragma unroll
            for (int i = 0; i < 4; i++)
                #pragma unroll
                for (int k = 0; k < 4; k++) acc[i][k] += a[i] * bb[k];
        }
        #pragma unroll
        for (int i = 0; i < 4; i++) {
            #pragma unroll
            for (int k = 0; k < 4; k++) {
                float v = acc[i][k] * SCALE_;
                __half hi, lo; split2(v, hi, lo);
                int r = r0 + ty * 4 + i;
                int col = h * 192 + tx * 4 + k;
                wuqeffc[(size_t)r * 1536 + col] = hi;
                wuqeffc[(size_t)(128 + r) * 1536 + col] = hi;
                wuqeffc[(size_t)(256 + r) * 1536 + col] = lo;
            }
        }
    } else if (bid < PB_OFF2) {
        int i = (bid - PB_OFF1) * 256 + tid;
        if (i < 128 * 512) {
            int r = i >> 9, rem = i & 511;
            int h = rem >> 6, cc = rem & 63;
            float v = (cc < 32) ? wuq[(size_t)r * 1024 + h * 96 + 64 + cc]
                                : wuq[(size_t)r * 1024 + 768 + h * 32 + (cc - 32)];
            v *= SCALE_;
            __half hi, lo; split2(v, hi, lo);
            int col = h * 192 + 128 + cc;
            wuqeffc[(size_t)r * 1536 + col] = hi;
            wuqeffc[(size_t)(128 + r) * 1536 + col] = hi;
            wuqeffc[(size_t)(256 + r) * 1536 + col] = lo;
        }
    } else if (bid < PB_OFF3) {
        int col = (bid - PB_OFF2) * 256 + tid;
        if (col < 1536) {
            int h = col / 192, c = col - h * 192;
            float v;
            if (c < 128) {
                float s = 0.f;
                const float* bq = buq + h * 96;
                const float* wk = wukuv + (size_t)c * 2560 + h * 64;
                #pragma unroll 8
                for (int j = 0; j < 64; j++) s += bq[j] * wk[j];
                v = s;
            } else if (c < 160) {
                v = buq[h * 96 + 64 + (c - 128)];
            } else {
                v = buq[768 + h * 32 + (c - 160)];
            }
            biase[col] = v * SCALE_;
        }
    } else if (bid < PB_OFF4) {
        int i = (bid - PB_OFF3) * 256 + tid;
        if (i < 8 * 128 * 256) {
            int h = i >> 15, rem = i & 32767;
            int c = rem >> 8, v = rem & 255;
            float val = wukuv[(size_t)c * 2560 + 512 + h * 256 + v];
            __half hi, lo; split2(val, hi, lo);
            __half* base = wfA + ((size_t)h * 128 + c) * 768;
            base[v] = hi;
            base[256 + v] = lo;
            base[512 + v] = hi;
        }
    } else if (bid < PB_OFF5) {
        int i4 = (bid - PB_OFF4) * 256 + tid;
        int elem = i4 * 4;
        int h = elem >> 18, rem = elem & 262143;
        int v = rem >> 10, o = rem & 1023;
        float4 val = *(const float4*)(wo + ((size_t)h * 256 + v) * 1024 + o);
        __half h0, l0, h1, l1, h2, l2, h3, l3;
        split2(val.x, h0, l0); split2(val.y, h1, l1);
        split2(val.z, h2, l2); split2(val.w, h3, l3);
        __half* base = wfB + (size_t)h * 768 * 1024;
        __half* p0 = base + (size_t)v * 1024 + o;
        __half* p1 = base + (size_t)(256 + v) * 1024 + o;
        __half* p2 = base + (size_t)(512 + v) * 1024 + o;
        *(__half2*)(p0 + 0) = __halves2half2(h0, h1);
        *(__half2*)(p0 + 2) = __halves2half2(h2, h3);
        *(__half2*)(p1 + 0) = __halves2half2(h0, h1);
        *(__half2*)(p1 + 2) = __halves2half2(h2, h3);
        *(__half2*)(p2 + 0) = __halves2half2(l0, l1);
        *(__half2*)(p2 + 2) = __halves2half2(l2, l3);
    } else {
        int bid2 = bid - PB_OFF5;
        int z = bid2 >> 2;
        int o = (bid2 & 3) * 256 + tid;
        float s = 0.f;
        #pragma unroll 8
        for (int r = z * 128; r < (z + 1) * 128; r++)
            s += bukuv[512 + r] * wo[(size_t)r * 1024 + o];
        bopart[(size_t)z * 1024 + o] = s;
    }
}

__global__ void prep_boeff2(const float* __restrict__ bo, const float* __restrict__ part,
                            float* __restrict__ be) {
    int o = blockIdx.x * 256 + threadIdx.x;
    float s = bo[o];
    #pragma unroll
    for (int z = 0; z < 16; z++) s += part[(size_t)z * 1024 + o];
    be[o] = s;
}

// ---------------- fp16 tensor-core GEMM: 3-stage cp.async pipeline -----------
// MODE 0: float out (bias only z==0). MODE 1: half out. MODE 2: qe layout + rope.
// Dynamic smem: 3 stages x (As 128x40 + Bs 32x136) halves = 56832 bytes.
#define HS_A (128 * 40)
#define HS_B (32 * 136)
#define HS_BYTES ((3 * HS_A + 3 * HS_B) * (int)sizeof(__half))
template <int MODE>
__global__ __launch_bounds__(256, 2) void hgemm(
    const __half* __restrict__ A, const __half* __restrict__ Bm,
    const float* __restrict__ bias, void* __restrict__ Cv, int M, int N, int K,
    int lda, size_t zA, size_t zB, size_t zC, const int* __restrict__ pos) {
    extern __shared__ __half hsm[];

    A += blockIdx.z * zA;
    Bm += blockIdx.z * zB;

    int tid = threadIdx.x, lane = tid & 31, w = tid >> 5;
    int wr = w >> 2, wc = w & 3;
    int row0 = blockIdx.y * 128, col0 = blockIdx.x * 128;

    float acc[16][4];
    #pragma unroll
    for (int i = 0; i < 16; i++)
        #pragma unroll
        for (int j = 0; j < 4; j++) acc[i][j] = 0.f;

    int nk = K >> 5;  // assumed >= 2

    auto load_tile = [&](int st, int k0) {
        const __half* Ab = A + (size_t)row0 * lda + k0;
        __half* Asd = hsm + st * HS_A;
        #pragma unroll
        for (int it = 0; it < 2; it++) {
            int e = it * 256 + tid;
            int r = e >> 2, c = (e & 3) * 8;
            cp16(Asd + r * 40 + c, Ab + (size_t)r * lda + c);
        }
        const __half* Bb = Bm + (size_t)k0 * N + col0;
        __half* Bsd = hsm + 3 * HS_A + st * HS_B;
        #pragma unroll
        for (int it = 0; it < 2; it++) {
            int e = it * 256 + tid;
            int r = e >> 4, c = (e & 15) * 8;
            cp16(Bsd + r * 136 + c, Bb + (size_t)r * N + c);
        }
    };

    // prologue: tiles 0, 1
    load_tile(0, 0);
    CP_COMMIT();
    load_tile(1, 32);
    CP_COMMIT();

    int cur = 0;
    for (int kt = 0; kt < nk; kt++) {
        CP_WAIT(1);          // tile kt landed
        __syncthreads();     // all warps done with stage (kt+2)%3's previous use
        if (kt + 2 < nk) load_tile((kt + 2) % 3, (kt + 2) << 5);
        CP_COMMIT();

        const __half* Asc = hsm + cur * HS_A;
        const __half* Bsc = hsm + 3 * HS_A + cur * HS_B;
        #pragma unroll
        for (int kk = 0; kk < 2; kk++) {
            uint32_t af[4][4], bf[2][4];
            #pragma unroll
            for (int mt = 0; mt < 4; mt++) {
                int r = wr * 64 + mt * 16 + (lane & 15);
                int c = kk * 16 + ((lane >> 4) << 3);
                ldsm_x4(af[mt], smem_u32(Asc + r * 40 + c));
            }
            #pragma unroll
            for (int nt2 = 0; nt2 < 2; nt2++) {
                int kr = kk * 16 + (lane & 7) + (lane & 8);
                int nc = wc * 32 + nt2 * 16 + ((lane >> 4) << 3);
                ldsm_x4_t(bf[nt2], smem_u32(Bsc + kr * 136 + nc));
            }
            #pragma unroll
            for (int mt = 0; mt < 4; mt++)
                #pragma unroll
                for (int nt = 0; nt < 4; nt++)
                    mma16816(acc[mt * 4 + nt], af[mt], bf[nt >> 1] + (nt & 1) * 2);
        }
        cur = (cur + 1 == 3) ? 0 : cur + 1;
    }

    float bz = (MODE == 0 && blockIdx.z > 0) ? 0.f : 1.f;
    #pragma unroll
    for (int mt = 0; mt < 4; mt++) {
        #pragma unroll
        for (int nt = 0; nt < 4; nt++) {
            int row = row0 + wr * 64 + mt * 16 + (lane >> 2);
            int col = col0 + wc * 32 + nt * 8 + (lane & 3) * 2;
            float b0 = bias[col] * bz, b1 = bias[col + 1] * bz;
            float v0 = acc[mt * 4 + nt][0] + b0;
            float v1 = acc[mt * 4 + nt][1] + b1;
            float v2 = acc[mt * 4 + nt][2] + b0;
            float v3 = acc[mt * 4 + nt][3] + b1;
            if (MODE == 0) {
                float* C = (float*)Cv + blockIdx.z * zC;
                *(float2*)(C + (size_t)row * N + col) = make_float2(v0, v1);
                *(float2*)(C + (size_t)(row + 8) * N + col) = make_float2(v2, v3);
            } else if (MODE == 1) {
                __half* C = (__half*)Cv + blockIdx.z * zC;
                *(__half2*)(C + (size_t)row * N + col) = __floats2half2_rn(v0, v1);
                *(__half2*)(C + (size_t)(row + 8) * N + col) = __floats2half2_rn(v2, v3);
            } else {
                __half* C = (__half*)Cv;
                int h = col / 192, c = col - h * 192;
                if (c >= 160) {
                    int i2 = (c - 160) >> 1;
                    float freq = powf(10000.f, -(float)(2 * i2) / 32.f);
                    float p0f = (float)pos[row], p1f = (float)pos[row + 8];
                    float a0 = p0f * freq, a1 = p1f * freq;
                    float c0 = cosf(a0), s0 = sinf(a0);
                    float c1 = cosf(a1), s1 = sinf(a1);
                    float t0 = v0 * c0 - v1 * s0, t1 = v0 * s0 + v1 * c0;
                    v0 = t0; v1 = t1;
                    t0 = v2 * c1 - v3 * s1; t1 = v2 * s1 + v3 * c1;
                    v2 = t0; v3 = t1;
                }
                int b = row >> 11, s = row & 2047;
                *(__half2*)(C + (((size_t)(b * 8 + h)) * S_ + s) * 192 + c) =
                    __floats2half2_rn(v0, v1);
                int row2 = row + 8;
                b = row2 >> 11; s = row2 & 2047;
                *(__half2*)(C + (((size_t)(b * 8 + h)) * S_ + s) * 192 + c) =
                    __floats2half2_rn(v2, v3);
            }
        }
    }
}

// ---------------- fused post-dqkv: sum split-K + 2x rmsnorm + k-rope ---------
__global__ void postproc(const float* __restrict__ dqkvA, const float* __restrict__ dqkvB,
                         const int* __restrict__ pos,
                         const float* __restrict__ qnw, const float* __restrict__ kvnw,
                         __half* __restrict__ cqcat, __half* __restrict__ keff) {
    __shared__ float r1[128], r2[128];
    int t = blockIdx.x, d = threadIdx.x;
    const float* rowA = dqkvA + (size_t)t * 384;
    const float* rowB = dqkvB + (size_t)t * 384;
    float qv = rowA[d] + rowB[d];
    float kvv = rowA[128 + d] + rowB[128 + d];
    r1[d] = qv * qv;
    r2[d] = kvv * kvv;
    __syncthreads();
    #pragma unroll
    for (int s = 64; s > 0; s >>= 1) {
        if (d < s) { r1[d] += r1[d + s]; r2[d] += r2[d + s]; }
        __syncthreads();
    }
    float invq = rsqrtf(r1[0] * (1.f / 128.f) + 1e-8f);
    float invk = rsqrtf(r2[0] * (1.f / 128.f) + 1e-8f);
    float cq = qnw[d] * qv * invq;
    __half hi, lo; split2(cq, hi, lo);
    __half* cr = cqcat + (size_t)t * 384;
    cr[d] = hi;
    cr[128 + d] = lo;
    cr[256 + d] = hi;
    keff[(size_t)t * 192 + d] = __float2half(kvnw[d] * kvv * invk);
    if (d < 32) {
        float p = (float)pos[t];
        float freq = powf(10000.f, -(float)(2 * d) / 64.f);
        float ang = p * freq;
        float c = cosf(ang), s = sinf(ang);
        float xe = rowA[256 + 2 * d] + rowB[256 + 2 * d];
        float xo = rowA[256 + 2 * d + 1] + rowB[256 + 2 * d + 1];
        keff[(size_t)t * 192 + 128 + 2 * d]     = __float2half(xe * c - xo * s);
        keff[(size_t)t * 192 + 128 + 2 * d + 1] = __float2half(xe * s + xo * c);
    }
}

// ---------------- absorbed flash attention -----------------------------------
#define KP 200
__global__ __launch_bounds__(256, 1) void flash_mla(
    const __half* __restrict__ Qe, const __half* __restrict__ Ke,
    __half* __restrict__ Out) {
    extern __shared__ __half sm[];   // 2 stages x 64 x KP (50 KB)

    int tid = threadIdx.x, lane = tid & 31, w = tid >> 5;
    int bh = blockIdx.y;
    int b = bh >> 3, h = bh & 7;
    int q0 = blockIdx.x * 128;

    {
        const __half* qbase = Qe + ((size_t)bh * S_ + q0) * 192;
        #pragma unroll
        for (int it = 0; it < 12; it++) {
            int e = it * 256 + tid;
            int r = e / 24, c = (e % 24) * 8;
            cp16(&sm[r * KP + c], qbase + (size_t)r * 192 + c);
        }
    }
    CP_COMMIT();
    CP_WAIT(0);
    __syncthreads();

    uint32_t qf[12][4];
    #pragma unroll
    for (int ks = 0; ks < 12; ks++) {
        int r = w * 16 + (lane & 15);
        int c = ks * 16 + ((lane >> 4) << 3);
        ldsm_x4(qf[ks], smem_u32(&sm[r * KP + c]));
    }
    __syncthreads();

    const __half* kbase = Ke + (size_t)b * S_ * 192;

    #pragma unroll
    for (int it = 0; it < 6; it++) {
        int e = it * 256 + tid;
        int r = e / 24, c = (e % 24) * 8;
        cp16(&sm[r * KP + c], kbase + (size_t)r * 192 + c);
    }
    CP_COMMIT();

    float m[2] = {-1e30f, -1e30f}, l[2] = {0.f, 0.f};
    float o[16][4];
    #pragma unroll
    for (int i = 0; i < 16; i++)
        #pragma unroll
        for (int j = 0; j < 4; j++) o[i][j] = 0.f;

    for (int kb = 0; kb < S_ / 64; kb++) {
        int cur = kb & 1;
        if (kb + 1 < S_ / 64) {
            const __half* kb2 = kbase + (size_t)(kb + 1) * 64 * 192;
            __half* Kd = sm + (cur ^ 1) * 64 * KP;
            #pragma unroll
            for (int it = 0; it < 6; it++) {
                int e = it * 256 + tid;
                int r = e / 24, c = (e % 24) * 8;
                cp16(&Kd[r * KP + c], kb2 + (size_t)r * 192 + c);
            }
        }
        CP_COMMIT();
        CP_WAIT(1);
        __syncthreads();

        const __half* Ks = sm + cur * 64 * KP;

        float s[8][4];
        #pragma unroll
        for (int i = 0; i < 8; i++)
            #pragma unroll
            for (int j = 0; j < 4; j++) s[i][j] = 0.f;
        #pragma unroll
        for (int ks = 0; ks < 12; ks++) {
            #pragma unroll
            for (int nt2 = 0; nt2 < 4; nt2++) {
                uint32_t bfr[4];
                int n = nt2 * 16 + ((lane >> 4) << 3) + (lane & 7);
                int k = ks * 16 + (lane & 8);
                ldsm_x4(bfr, smem_u32(&Ks[n * KP + k]));
                mma16816(s[2 * nt2],     qf[ks], bfr + 0);
                mma16816(s[2 * nt2 + 1], qf[ks], bfr + 2);
            }
        }

        #pragma unroll
        for (int rr = 0; rr < 2; rr++) {
            float mx = -1e30f;
            #pragma unroll
            for (int j = 0; j < 8; j++)
                mx = fmaxf(mx, fmaxf(s[j][2 * rr], s[j][2 * rr + 1]));
            mx = fmaxf(mx, __shfl_xor_sync(0xffffffffu, mx, 1));
            mx = fmaxf(mx, __shfl_xor_sync(0xffffffffu, mx, 2));
            float m_new = fmaxf(m[rr], mx);
            float alpha = __expf(m[rr] - m_new);
            float tsum = 0.f;
            #pragma unroll
            for (int j = 0; j < 8; j++) {
                float p0 = __expf(s[j][2 * rr] - m_new);
                float p1 = __expf(s[j][2 * rr + 1] - m_new);
                s[j][2 * rr] = p0;
                s[j][2 * rr + 1] = p1;
                tsum += p0 + p1;
            }
            tsum += __shfl_xor_sync(0xffffffffu, tsum, 1);
            tsum += __shfl_xor_sync(0xffffffffu, tsum, 2);
            l[rr] = l[rr] * alpha + tsum;
            m[rr] = m_new;
            #pragma unroll
            for (int j = 0; j < 16; j++) {
                o[j][2 * rr] *= alpha;
                o[j][2 * rr + 1] *= alpha;
            }
        }

        uint32_t pf[4][4];
        #pragma unroll
        for (int kk = 0; kk < 4; kk++) {
            pf[kk][0] = pack_h2(s[2 * kk][0],     s[2 * kk][1]);
            pf[kk][1] = pack_h2(s[2 * kk][2],     s[2 * kk][3]);
            pf[kk][2] = pack_h2(s[2 * kk + 1][0], s[2 * kk + 1][1]);
            pf[kk][3] = pack_h2(s[2 * kk + 1][2], s[2 * kk + 1][3]);
        }

        #pragma unroll
        for (int kk = 0; kk < 4; kk++) {
            #pragma unroll
            for (int nt2 = 0; nt2 < 8; nt2++) {
                uint32_t bfr[4];
                int k = kk * 16 + (lane & 7) + (lane & 8);
                int n = nt2 * 16 + ((lane >> 4) << 3);
                ldsm_x4_t(bfr, smem_u32(&Ks[k * KP + n]));
                mma16816(o[2 * nt2],     pf[kk], bfr + 0);
                mma16816(o[2 * nt2 + 1], pf[kk], bfr + 2);
            }
        }
        __syncthreads();
    }

    #pragma unroll
    for (int rr = 0; rr < 2; rr++) {
        float inv = 1.f / l[rr];
        int row = q0 + w * 16 + (lane >> 2) + rr * 8;
        size_t base = ((size_t)(b * S_) + row) * 1024 + h * 128;
        #pragma unroll
        for (int j = 0; j < 16; j++) {
            int c = j * 8 + (lane & 3) * 2;
            *(__half2*)&Out[base + c] =
                __floats2half2_rn(o[j][2 * rr] * inv, o[j][2 * rr + 1] * inv);
        }
    }
}

// ---------------- launch -----------------------------------------------------
extern "C" void kernel_launch(void* const* d_in, const int* in_sizes, int n_in,
                              void* d_out, int out_size) {
    const float* x        = (const float*)d_in[0];
    const int*   pos      = (const int*)d_in[1];
    const float* w_dq_w   = (const float*)d_in[2];
    const float* w_dq_b   = (const float*)d_in[3];
    const float* q_norm_w = (const float*)d_in[4];
    const float* w_uq_w   = (const float*)d_in[5];
    const float* w_uq_b   = (const float*)d_in[6];
    const float* w_dkv_w  = (const float*)d_in[7];
    const float* w_dkv_b  = (const float*)d_in[8];
    const float* kv_norm_w= (const float*)d_in[9];
    const float* w_ukuv_w = (const float*)d_in[10];
    const float* w_ukuv_b = (const float*)d_in[11];
    const float* w_o_w    = (const float*)d_in[12];
    const float* w_o_b    = (const float*)d_in[13];
    float* out = (float*)d_out;

    __half *xcat, *wdqkv, *cqcat, *wuqeff, *qe, *keff, *attnlat, *wfA, *wfB, *wfused;
    float *dqkv, *bias_dqkv, *biaseff, *bopart, *boeff, *zb;
    cudaGetSymbolAddress((void**)&xcat,     g_xcat);
    cudaGetSymbolAddress((void**)&wdqkv,    g_wdqkv);
    cudaGetSymbolAddress((void**)&bias_dqkv,g_bias_dqkv);
    cudaGetSymbolAddress((void**)&dqkv,     g_dqkv);
    cudaGetSymbolAddress((void**)&cqcat,    g_cqcat);
    cudaGetSymbolAddress((void**)&wuqeff,   g_wuqeff);
    cudaGetSymbolAddress((void**)&biaseff,  g_biaseff);
    cudaGetSymbolAddress((void**)&qe,       g_qe);
    cudaGetSymbolAddress((void**)&keff,     g_keff);
    cudaGetSymbolAddress((void**)&attnlat,  g_attnlat);
    cudaGetSymbolAddress((void**)&wfA,      g_wfA);
    cudaGetSymbolAddress((void**)&wfB,      g_wfB);
    cudaGetSymbolAddress((void**)&wfused,   g_wfused);
    cudaGetSymbolAddress((void**)&bopart,   g_bopart);
    cudaGetSymbolAddress((void**)&boeff,    g_boeff);
    cudaGetSymbolAddress((void**)&zb,       g_zb);

    // one-time host resources (created on the uncaptured correctness call)
    static cudaStream_t s2 = nullptr;
    static cudaEvent_t eFork = nullptr, eJ1 = nullptr, eJ2 = nullptr;
    static bool attr_done = false;
    if (!s2) {
        cudaStreamCreateWithFlags(&s2, cudaStreamNonBlocking);
        cudaEventCreateWithFlags(&eFork, cudaEventDisableTiming);
        cudaEventCreateWithFlags(&eJ1, cudaEventDisableTiming);
        cudaEventCreateWithFlags(&eJ2, cudaEventDisableTiming);
    }
    if (!attr_done) {
        cudaFuncSetAttribute(hgemm<0>, cudaFuncAttributeMaxDynamicSharedMemorySize, HS_BYTES);
        cudaFuncSetAttribute(hgemm<1>, cudaFuncAttributeMaxDynamicSharedMemorySize, HS_BYTES);
        cudaFuncSetAttribute(hgemm<2>, cudaFuncAttributeMaxDynamicSharedMemorySize, HS_BYTES);
        cudaFuncSetAttribute(flash_mla, cudaFuncAttributeMaxDynamicSharedMemorySize,
                             128 * KP * (int)sizeof(__half));
        attr_done = true;
    }

    // ---- fork: branch B (weight prep + wfused) on s2 ----
    cudaEventRecord(eFork, 0);
    cudaStreamWaitEvent(s2, eFork, 0);

    prep_b<<<PB_TOTAL, 256, 0, s2>>>(w_uq_w, w_uq_b, w_ukuv_w, w_ukuv_b, w_o_w,
                                     wuqeff, biaseff, wfA, wfB, bopart);
    cudaEventRecord(eJ1, s2);   // wuqeff + biaseff ready
    prep_boeff2<<<4, 256, 0, s2>>>(w_o_b, bopart, boeff);
    hgemm<1><<<dim3(8, 1, 8), 256, HS_BYTES, s2>>>(
        wfA, wfB, zb, wfused, 128, 1024, 768, 768,
        (size_t)128 * 768, (size_t)768 * 1024, (size_t)128 * 1024, nullptr);
    cudaEventRecord(eJ2, s2);   // wfused + boeff ready

    // ---- branch A (token path) on default stream ----
    prep_a<<<PA_TOTAL, 256>>>(x, w_dq_w, w_dkv_w, w_dq_b, w_dkv_b,
                              xcat, wdqkv, bias_dqkv);
    // fused dq+dkv, split-K batched over z (each K=1536, lda=3072)
    hgemm<0><<<dim3(3, 32, 2), 256, HS_BYTES>>>(
        xcat, wdqkv, bias_dqkv, dqkv, T_, 384, 1536, 3072,
        (size_t)1536, (size_t)1536 * 384, (size_t)T_ * 384, nullptr);
    postproc<<<T_, 128>>>(dqkv, dqkv + (size_t)T_ * 384, pos, q_norm_w, kv_norm_w,
                          cqcat, keff);

    cudaStreamWaitEvent(0, eJ1, 0);   // need wuqeff/biaseff
    hgemm<2><<<dim3(12, 32, 1), 256, HS_BYTES>>>(
        cqcat, wuqeff, biaseff, qe, T_, 1536, 384, 384, 0, 0, 0, pos);

    flash_mla<<<dim3(S_ / 128, 16), 256, 128 * KP * sizeof(__half)>>>(qe, keff, attnlat);

    cudaStreamWaitEvent(0, eJ2, 0);   // need wfused/boeff
    hgemm<0><<<dim3(8, 32, 1), 256, HS_BYTES>>>(
        attnlat, wfused, boeff, out, T_, 1024, 1024, 1024, 0, 0, 0, nullptr);
}